// round 11
// baseline (speedup 1.0000x reference)
#include <cuda_runtime.h>
#include <cuda_fp16.h>
#include <math.h>
#include <stdint.h>

#define BB 4
#define CC 256
#define CI 128
#define NP 4096
#define LOG2E 1.4426950408889634f

typedef unsigned long long u64;
typedef unsigned int u32;

// Scratch (device globals: allocation-free rule)
__device__ __half g_xh[BB * CC * NP];  // x hi : (b, c, n)
__device__ __half g_xl[BB * CC * NP];  // x lo
__device__ __half g_twh[CI * CC], g_twl[CI * CC];
__device__ __half g_pwh[CI * CC], g_pwl[CI * CC];
__device__ __half g_gwh[CI * CC], g_gwl[CI * CC];
__device__ __half g_wwh[CC * CI], g_wwl[CC * CI];
__device__ __half g_qh[BB * NP * CI];  // theta(x)*log2e hi         : (b, n, o)
__device__ __half g_qc[BB * NP * CI];  // qh/64 + ql (correction)   : (b, n, o)
__device__ __half g_kh[BB * NP * CI];  // phi(x) hi                 : (b, m, o)
__device__ __half g_kc[BB * NP * CI];  // kh + 64*kl (correction)   : (b, m, o)
__device__ __half g_vt[BB * CI * NP];  // g(x) transposed           : (b, o, m)
__device__ float  g_po[2 * BB * NP * CI];  // unnormalized partial O per kv-split
__device__ float  g_pm[2 * BB * NP];       // partial running max (log2 domain)
__device__ float  g_pl[2 * BB * NP];       // partial running sum

// ---------------- helpers ----------------
__device__ __forceinline__ float ex2(float x) {
    float y;
    asm("ex2.approx.ftz.f32 %0, %1;" : "=f"(y) : "f"(x));
    return y;
}
__device__ __forceinline__ u32 smem_u32(const void* p) {
    u32 a;
    asm("{ .reg .u64 t; cvta.to.shared.u64 t, %1; cvt.u32.u64 %0, t; }" : "=r"(a) : "l"(p));
    return a;
}
__device__ __forceinline__ u32 h2u(__half a, __half b) {
    __half2 h = __halves2half2(a, b);
    return *(u32*)&h;
}

// ---------------- mma.sync / ldmatrix / cp.async ----------------
__device__ __forceinline__ void ldm4(u32& r0, u32& r1, u32& r2, u32& r3, u32 addr) {
    asm volatile("ldmatrix.sync.aligned.m8n8.x4.shared.b16 {%0,%1,%2,%3}, [%4];"
                 : "=r"(r0), "=r"(r1), "=r"(r2), "=r"(r3) : "r"(addr));
}
__device__ __forceinline__ void ldm4t(u32& r0, u32& r1, u32& r2, u32& r3, u32 addr) {
    asm volatile("ldmatrix.sync.aligned.m8n8.x4.trans.shared.b16 {%0,%1,%2,%3}, [%4];"
                 : "=r"(r0), "=r"(r1), "=r"(r2), "=r"(r3) : "r"(addr));
}
__device__ __forceinline__ void mma16816(float* c, u32 a0, u32 a1, u32 a2, u32 a3,
                                         u32 b0, u32 b1) {
    asm volatile(
        "mma.sync.aligned.m16n8k16.row.col.f32.f16.f16.f32 "
        "{%0,%1,%2,%3}, {%4,%5,%6,%7}, {%8,%9}, {%0,%1,%2,%3};"
        : "+f"(c[0]), "+f"(c[1]), "+f"(c[2]), "+f"(c[3])
        : "r"(a0), "r"(a1), "r"(a2), "r"(a3), "r"(b0), "r"(b1));
}
__device__ __forceinline__ void cpa(u32 s, const void* g) {
    asm volatile("cp.async.cg.shared.global [%0], [%1], 16;" :: "r"(s), "l"(g));
}
#define CP_COMMIT() asm volatile("cp.async.commit_group;")
#define CP_WAIT1()  asm volatile("cp.async.wait_group 1;")
#define CP_WAIT0()  asm volatile("cp.async.wait_group 0;")

#define SWZ256(x) ((x) ^ (((x) >> 4) & 0x70))   // 256B rows
#define SWZ128(x) ((x) ^ (((x) >> 3) & 0x70))   // 128B rows

#define HONE 0x3C003C00u   // half2(1.0, 1.0)

// =================================================================
// Kernel 0: fp32 -> fp16 hi/lo conversion, single launch for x + 4 weights.
// =================================================================
__global__ __launch_bounds__(256) void conv_all(
    const float* __restrict__ x,
    const float* __restrict__ tw, const float* __restrict__ pw,
    const float* __restrict__ gw, const float* __restrict__ ww)
{
    int bid = blockIdx.x;
    const float* src;
    __half *dh, *dl;
    int i;
    if (bid < 4096) {
        src = x; dh = g_xh; dl = g_xl;
        i = bid * 1024 + threadIdx.x * 4;
    } else {
        int wsel = (bid - 4096) >> 5;
        i = ((bid - 4096) & 31) * 1024 + threadIdx.x * 4;
        src = (wsel == 0) ? tw : (wsel == 1) ? pw : (wsel == 2) ? gw : ww;
        dh  = (wsel == 0) ? g_twh : (wsel == 1) ? g_pwh : (wsel == 2) ? g_gwh : g_wwh;
        dl  = (wsel == 0) ? g_twl : (wsel == 1) ? g_pwl : (wsel == 2) ? g_gwl : g_wwl;
    }
    float4 v = *(const float4*)&src[i];
    __half h0 = __float2half_rn(v.x), h1 = __float2half_rn(v.y);
    __half h2 = __float2half_rn(v.z), h3 = __float2half_rn(v.w);
    __half l0 = __float2half_rn(v.x - __half2float(h0));
    __half l1 = __float2half_rn(v.y - __half2float(h1));
    __half l2 = __float2half_rn(v.z - __half2float(h2));
    __half l3 = __float2half_rn(v.w - __half2float(h3));
    *(uint2*)&dh[i] = make_uint2(h2u(h0, h1), h2u(h2, h3));
    *(uint2*)&dl[i] = make_uint2(h2u(l0, l1), h2u(l2, l3));
}

// =================================================================
// Kernel 1: QKV projections, X-resident mega kernel (R10, unchanged).
// =================================================================
#define PJX_XH   0
#define PJX_XL   65536
#define PJX_W0   131072
#define PJX_W1   163840
#define PJX_SMEM 196608

__device__ __forceinline__ void stage_w(u32 wbase, const __half* Wh,
                                        const __half* Wl, int c0, int t)
{
#pragma unroll
    for (int i = 0; i < 4; i++) {
        int id = i * 256 + t;
        int row = id >> 3, ch = id & 7;
        u32 sw = SWZ128(row * 128 + ch * 16);
        cpa(wbase + sw,         Wh + (size_t)row * CC + c0 + ch * 8);
        cpa(wbase + 16384 + sw, Wl + (size_t)row * CC + c0 + ch * 8);
    }
}

__global__ __launch_bounds__(256, 1) void proj_kernel(
    const float* __restrict__ tb, const float* __restrict__ pb,
    const float* __restrict__ gb)
{
    extern __shared__ char ps[];
    __shared__ float bias_s[3][128];
    const u32 s32 = smem_u32(ps);
    const int b  = blockIdx.y;
    const int n0 = blockIdx.x * 128;
    const int t  = threadIdx.x;
    const int lane = t & 31;
    const int w  = t >> 5;
    const int wm = w & 3;
    const int wn = w >> 2;

    const int lrow = lane & 15;
    const int lcol = (lane >> 4) * 16;
    const int g    = lane >> 2;
    const int c2   = (lane & 3) * 2;
    const int trow = ((lane >> 4) << 3) + (lane & 7);
    const int tcol = ((lane >> 3) & 1) * 8;

    const __half* WH[3] = {g_twh, g_pwh, g_gwh};
    const __half* WL[3] = {g_twl, g_pwl, g_gwl};
    const __half* Xh = g_xh + (size_t)b * CC * NP;
    const __half* Xl = g_xl + (size_t)b * CC * NP;

    if (t < 128) {
        bias_s[0][t] = tb[t];
        bias_s[1][t] = pb[t];
        bias_s[2][t] = gb[t];
    }

    // ---- prologue: stage X (once) + W chunks 0,1 ----
#pragma unroll
    for (int i = 0; i < 16; i++) {
        int id = i * 256 + t;
        int row = id >> 4, ch = id & 15;
        u32 sw = SWZ256(row * 256 + ch * 16);
        cpa(s32 + PJX_XH + sw, Xh + (size_t)row * NP + n0 + ch * 8);
        cpa(s32 + PJX_XL + sw, Xl + (size_t)row * NP + n0 + ch * 8);
    }
    stage_w(s32 + PJX_W0, WH[0], WL[0], 0, t);
    CP_COMMIT();
    stage_w(s32 + PJX_W1, WH[0], WL[0], 64, t);
    CP_COMMIT();

    float acc[2][8][4];

    for (int q = 0; q < 12; q++) {
        const int z  = q >> 2;
        const int c0 = (q & 3) * 64;
        const u32 wb = s32 + ((q & 1) ? PJX_W1 : PJX_W0);

        if ((q & 3) == 0) {
#pragma unroll
            for (int mf = 0; mf < 2; mf++)
#pragma unroll
                for (int nf = 0; nf < 8; nf++)
#pragma unroll
                    for (int p = 0; p < 4; p++) acc[mf][nf][p] = 0.0f;
        }

        CP_WAIT1();
        __syncthreads();

#pragma unroll
        for (int kc = 0; kc < 4; kc++) {
            u32 Ah[2][4], Al[2][4], B[4][4];
#pragma unroll
            for (int mf = 0; mf < 2; mf++)
                ldm4t(Ah[mf][0], Ah[mf][1], Ah[mf][2], Ah[mf][3],
                      s32 + PJX_XH + SWZ256((c0 + kc * 16 + trow) * 256 + (wm * 32 + mf * 16 + tcol) * 2));
#pragma unroll
            for (int bf = 0; bf < 4; bf++)
                ldm4(B[bf][0], B[bf][1], B[bf][2], B[bf][3],
                     wb + SWZ128((wn * 64 + bf * 16 + lrow) * 128 + kc * 32 + lcol));
#pragma unroll
            for (int mf = 0; mf < 2; mf++)
#pragma unroll
                for (int bf = 0; bf < 4; bf++) {
                    mma16816(acc[mf][2 * bf],     Ah[mf][0], Ah[mf][1], Ah[mf][2], Ah[mf][3], B[bf][0], B[bf][2]);
                    mma16816(acc[mf][2 * bf + 1], Ah[mf][0], Ah[mf][1], Ah[mf][2], Ah[mf][3], B[bf][1], B[bf][3]);
                }
#pragma unroll
            for (int mf = 0; mf < 2; mf++)
                ldm4t(Al[mf][0], Al[mf][1], Al[mf][2], Al[mf][3],
                      s32 + PJX_XL + SWZ256((c0 + kc * 16 + trow) * 256 + (wm * 32 + mf * 16 + tcol) * 2));
#pragma unroll
            for (int mf = 0; mf < 2; mf++)
#pragma unroll
                for (int bf = 0; bf < 4; bf++) {
                    mma16816(acc[mf][2 * bf],     Al[mf][0], Al[mf][1], Al[mf][2], Al[mf][3], B[bf][0], B[bf][2]);
                    mma16816(acc[mf][2 * bf + 1], Al[mf][0], Al[mf][1], Al[mf][2], Al[mf][3], B[bf][1], B[bf][3]);
                }
#pragma unroll
            for (int bf = 0; bf < 4; bf++)
                ldm4(B[bf][0], B[bf][1], B[bf][2], B[bf][3],
                     wb + 16384 + SWZ128((wn * 64 + bf * 16 + lrow) * 128 + kc * 32 + lcol));
#pragma unroll
            for (int mf = 0; mf < 2; mf++)
#pragma unroll
                for (int bf = 0; bf < 4; bf++) {
                    mma16816(acc[mf][2 * bf],     Ah[mf][0], Ah[mf][1], Ah[mf][2], Ah[mf][3], B[bf][0], B[bf][2]);
                    mma16816(acc[mf][2 * bf + 1], Ah[mf][0], Ah[mf][1], Ah[mf][2], Ah[mf][3], B[bf][1], B[bf][3]);
                }
        }

        __syncthreads();
        if (q + 2 < 12) {
            int q2 = q + 2;
            stage_w(s32 + ((q2 & 1) ? PJX_W1 : PJX_W0),
                    WH[q2 >> 2], WL[q2 >> 2], (q2 & 3) * 64, t);
        }
        CP_COMMIT();

        if ((q & 3) == 3) {
            if (z == 2) {
#pragma unroll
                for (int mf = 0; mf < 2; mf++) {
                    int nl = wm * 32 + mf * 16 + g;
#pragma unroll
                    for (int nf = 0; nf < 8; nf++) {
                        int o = wn * 64 + nf * 8 + c2;
                        __half h00 = __float2half_rn(acc[mf][nf][0] + bias_s[2][o]);
                        __half h01 = __float2half_rn(acc[mf][nf][1] + bias_s[2][o + 1]);
                        __half h10 = __float2half_rn(acc[mf][nf][2] + bias_s[2][o]);
                        __half h11 = __float2half_rn(acc[mf][nf][3] + bias_s[2][o + 1]);
                        *(__half*)(ps + (o * 128 + nl) * 2)           = h00;
                        *(__half*)(ps + ((o + 1) * 128 + nl) * 2)     = h01;
                        *(__half*)(ps + (o * 128 + nl + 8) * 2)       = h10;
                        *(__half*)(ps + ((o + 1) * 128 + nl + 8) * 2) = h11;
                    }
                }
                __syncthreads();
                int o = t >> 1, part = t & 1;
                __half* dst = g_vt + ((size_t)b * CI + o) * NP + n0 + part * 64;
#pragma unroll
                for (int k = 0; k < 8; k++)
                    *(uint4*)&dst[k * 8] = *(uint4*)(ps + (o * 128 + part * 64 + k * 8) * 2);
            } else {
                __half* dh = (z == 0) ? g_qh : g_kh;
                __half* dc = (z == 0) ? g_qc : g_kc;
                const float sc = (z == 0) ? LOG2E : 1.0f;
                const size_t bq = (size_t)b * NP + n0;
#pragma unroll
                for (int mf = 0; mf < 2; mf++) {
                    int nl = wm * 32 + mf * 16 + g;
#pragma unroll
                    for (int nf = 0; nf < 8; nf++) {
                        int o = wn * 64 + nf * 8 + c2;
                        float bv0 = bias_s[z][o], bv1 = bias_s[z][o + 1];
                        float v[4];
                        v[0] = (acc[mf][nf][0] + bv0) * sc;
                        v[1] = (acc[mf][nf][1] + bv1) * sc;
                        v[2] = (acc[mf][nf][2] + bv0) * sc;
                        v[3] = (acc[mf][nf][3] + bv1) * sc;
                        __half hh[4], cc[4];
#pragma unroll
                        for (int p = 0; p < 4; p++) {
                            __half h = __float2half_rn(v[p]);
                            float  hf = __half2float(h);
                            float  l  = v[p] - hf;
                            hh[p] = h;
                            cc[p] = (z == 0) ? __float2half_rn(hf * 0.015625f + l)
                                             : __float2half_rn(hf + 64.0f * l);
                        }
                        size_t i0 = (bq + nl) * CI + o;
                        size_t i1 = i0 + (size_t)8 * CI;
                        *(u32*)&dh[i0] = h2u(hh[0], hh[1]);
                        *(u32*)&dc[i0] = h2u(cc[0], cc[1]);
                        *(u32*)&dh[i1] = h2u(hh[2], hh[3]);
                        *(u32*)&dc[i1] = h2u(cc[2], cc[3]);
                    }
                }
            }
        }
    }
}

// =================================================================
// Kernel 2: flash attention (R8/R10 version, unchanged).
// =================================================================
#define OFF_QH 0
#define OFF_QC 32768
#define OFF_KH 65536
#define OFF_KC 81920
#define OFF_V  98304
#define SMEM_ATTN 114688
#define KV_TILES 32

__device__ __forceinline__ void load_k(u32 s32, int m0,
                                       const __half* gkh, const __half* gkc, int t)
{
#pragma unroll
    for (int i = 0; i < 8; i++) {
        int id = i * 128 + t;
        int row = id >> 4, c = id & 15;
        u32 sw = SWZ256(row * 256 + c * 16);
        cpa(s32 + OFF_KH + sw, gkh + (size_t)(m0 + row) * CI + c * 8);
        cpa(s32 + OFF_KC + sw, gkc + (size_t)(m0 + row) * CI + c * 8);
    }
}
__device__ __forceinline__ void load_v(u32 s32, int m0, const __half* gvt, int t)
{
#pragma unroll
    for (int i = 0; i < 8; i++) {
        int id = i * 128 + t;
        int row = id >> 3, c = id & 7;
        cpa(s32 + OFF_V + SWZ128(row * 128 + c * 16), gvt + (size_t)row * NP + m0 + c * 8);
    }
}

__global__ __launch_bounds__(128, 2) void attn_kernel()
{
    extern __shared__ __align__(128) char smem[];
    const u32 s32   = smem_u32(smem);
    const int t     = threadIdx.x;
    const int lane  = t & 31;
    const int wr    = (t >> 5) * 32;
    const int row0  = blockIdx.x * 128;
    const int split = blockIdx.y;
    const int b     = blockIdx.z;
    const int kv0   = split * (NP / 2);

    const int lrow = lane & 15;
    const int lcol = (lane >> 4) * 16;
    const int g    = lane >> 2;
    const int c2   = (lane & 3) * 2;

    const __half* gqh = g_qh + ((size_t)b * NP + row0) * CI;
    const __half* gqc = g_qc + ((size_t)b * NP + row0) * CI;
    const __half* gkh = g_kh + ((size_t)b * NP + kv0) * CI;
    const __half* gkc = g_kc + ((size_t)b * NP + kv0) * CI;
    const __half* gvt = g_vt + (size_t)b * CI * NP + kv0;

#pragma unroll
    for (int i = 0; i < 16; i++) {
        int id = i * 128 + t;
        int row = id >> 4, c = id & 15;
        u32 sw = SWZ256(row * 256 + c * 16);
        cpa(s32 + OFF_QH + sw, gqh + (size_t)row * CI + c * 8);
        cpa(s32 + OFF_QC + sw, gqc + (size_t)row * CI + c * 8);
    }
    load_k(s32, 0, gkh, gkc, t);
    CP_COMMIT();
    load_v(s32, 0, gvt, t);
    CP_COMMIT();

    float o[2][16][4];
#pragma unroll
    for (int mf = 0; mf < 2; mf++)
#pragma unroll
        for (int nf = 0; nf < 16; nf++)
#pragma unroll
            for (int q = 0; q < 4; q++) o[mf][nf][q] = 0.0f;
    float mrun[2][2] = {{-1e30f, -1e30f}, {-1e30f, -1e30f}};
    float lrun[2][2] = {{0.0f, 0.0f}, {0.0f, 0.0f}};

    for (int tile = 0; tile < KV_TILES; tile++) {
        CP_WAIT1();
        __syncthreads();

        float s[2][8][4];
#pragma unroll
        for (int mf = 0; mf < 2; mf++)
#pragma unroll
            for (int nf = 0; nf < 8; nf++)
#pragma unroll
                for (int q = 0; q < 4; q++) s[mf][nf][q] = 0.0f;

#pragma unroll
        for (int kc = 0; kc < 8; kc++) {
            u32 qa[2][4];
#pragma unroll
            for (int mf = 0; mf < 2; mf++)
                ldm4(qa[mf][0], qa[mf][1], qa[mf][2], qa[mf][3],
                     s32 + OFF_QH + SWZ256((wr + mf * 16 + lrow) * 256 + kc * 32 + lcol));
#pragma unroll
            for (int nb = 0; nb < 4; nb++) {
                u32 k0, k1, k2, k3;
                ldm4(k0, k1, k2, k3,
                     s32 + OFF_KH + SWZ256((nb * 16 + lrow) * 256 + kc * 32 + lcol));
#pragma unroll
                for (int mf = 0; mf < 2; mf++) {
                    mma16816(s[mf][2 * nb],     qa[mf][0], qa[mf][1], qa[mf][2], qa[mf][3], k0, k2);
                    mma16816(s[mf][2 * nb + 1], qa[mf][0], qa[mf][1], qa[mf][2], qa[mf][3], k1, k3);
                }
            }
        }
#pragma unroll
        for (int mf = 0; mf < 2; mf++)
#pragma unroll
            for (int nf = 0; nf < 8; nf++)
#pragma unroll
                for (int q = 0; q < 4; q++) s[mf][nf][q] *= 0.984375f;

#pragma unroll
        for (int kc = 0; kc < 8; kc++) {
            u32 qa[2][4];
#pragma unroll
            for (int mf = 0; mf < 2; mf++)
                ldm4(qa[mf][0], qa[mf][1], qa[mf][2], qa[mf][3],
                     s32 + OFF_QC + SWZ256((wr + mf * 16 + lrow) * 256 + kc * 32 + lcol));
#pragma unroll
            for (int nb = 0; nb < 4; nb++) {
                u32 k0, k1, k2, k3;
                ldm4(k0, k1, k2, k3,
                     s32 + OFF_KC + SWZ256((nb * 16 + lrow) * 256 + kc * 32 + lcol));
#pragma unroll
                for (int mf = 0; mf < 2; mf++) {
                    mma16816(s[mf][2 * nb],     qa[mf][0], qa[mf][1], qa[mf][2], qa[mf][3], k0, k2);
                    mma16816(s[mf][2 * nb + 1], qa[mf][0], qa[mf][1], qa[mf][2], qa[mf][3], k1, k3);
                }
            }
        }

        __syncthreads();
        if (tile + 1 < KV_TILES) load_k(s32, (tile + 1) * 64, gkh, gkc, t);
        CP_COMMIT();

        float corr[2][2];
        u32   p[2][4][4];
#pragma unroll
        for (int mf = 0; mf < 2; mf++) {
            float mx0 = fmaxf(s[mf][0][0], s[mf][0][1]);
            float mx1 = fmaxf(s[mf][0][2], s[mf][0][3]);
#pragma unroll
            for (int nf = 1; nf < 8; nf++) {
                mx0 = fmaxf(mx0, fmaxf(s[mf][nf][0], s[mf][nf][1]));
                mx1 = fmaxf(mx1, fmaxf(s[mf][nf][2], s[mf][nf][3]));
            }
            mx0 = fmaxf(mx0, __shfl_xor_sync(0xffffffffu, mx0, 1));
            mx0 = fmaxf(mx0, __shfl_xor_sync(0xffffffffu, mx0, 2));
            mx1 = fmaxf(mx1, __shfl_xor_sync(0xffffffffu, mx1, 1));
            mx1 = fmaxf(mx1, __shfl_xor_sync(0xffffffffu, mx1, 2));
            float mnew0 = fmaxf(mrun[mf][0], mx0);
            float mnew1 = fmaxf(mrun[mf][1], mx1);
            corr[mf][0] = ex2(mrun[mf][0] - mnew0);
            corr[mf][1] = ex2(mrun[mf][1] - mnew1);
            mrun[mf][0] = mnew0;
            mrun[mf][1] = mnew1;

#pragma unroll
            for (int kc2 = 0; kc2 < 4; kc2++) {
#pragma unroll
                for (int half = 0; half < 2; half++) {
                    int nf = 2 * kc2 + half;
                    float e0 = ex2(s[mf][nf][0] - mnew0);
                    float e1 = ex2(s[mf][nf][1] - mnew0);
                    float e2 = ex2(s[mf][nf][2] - mnew1);
                    float e3 = ex2(s[mf][nf][3] - mnew1);
                    p[mf][kc2][2 * half]     = h2u(__float2half_rn(e0), __float2half_rn(e1));
                    p[mf][kc2][2 * half + 1] = h2u(__float2half_rn(e2), __float2half_rn(e3));
                }
            }
        }

        float lc[2][4] = {{0.0f, 0.0f, 0.0f, 0.0f}, {0.0f, 0.0f, 0.0f, 0.0f}};
#pragma unroll
        for (int mf = 0; mf < 2; mf++)
#pragma unroll
            for (int kc2 = 0; kc2 < 4; kc2++)
                mma16816(lc[mf], p[mf][kc2][0], p[mf][kc2][1],
                         p[mf][kc2][2], p[mf][kc2][3], HONE, HONE);
#pragma unroll
        for (int mf = 0; mf < 2; mf++) {
            lrun[mf][0] = lrun[mf][0] * corr[mf][0] + lc[mf][0];
            lrun[mf][1] = lrun[mf][1] * corr[mf][1] + lc[mf][2];
        }

        if (__any_sync(0xffffffffu,
                       fminf(fminf(corr[0][0], corr[0][1]),
                             fminf(corr[1][0], corr[1][1])) < 0.99999f)) {
#pragma unroll
            for (int mf = 0; mf < 2; mf++)
#pragma unroll
                for (int nf = 0; nf < 16; nf++) {
                    o[mf][nf][0] *= corr[mf][0]; o[mf][nf][1] *= corr[mf][0];
                    o[mf][nf][2] *= corr[mf][1]; o[mf][nf][3] *= corr[mf][1];
                }
        }

        CP_WAIT1();
        __syncthreads();

#pragma unroll
        for (int kc2 = 0; kc2 < 4; kc2++) {
#pragma unroll
            for (int dg = 0; dg < 8; dg++) {
                u32 v0, v1, v2, v3;
                ldm4(v0, v1, v2, v3,
                     s32 + OFF_V + SWZ128((dg * 16 + lrow) * 128 + kc2 * 32 + lcol));
#pragma unroll
                for (int mf = 0; mf < 2; mf++) {
                    mma16816(o[mf][2 * dg],
                             p[mf][kc2][0], p[mf][kc2][1], p[mf][kc2][2], p[mf][kc2][3], v0, v2);
                    mma16816(o[mf][2 * dg + 1],
                             p[mf][kc2][0], p[mf][kc2][1], p[mf][kc2][2], p[mf][kc2][3], v1, v3);
                }
            }
        }

        __syncthreads();
        if (tile + 1 < KV_TILES) load_v(s32, (tile + 1) * 64, gvt, t);
        CP_COMMIT();
    }

    float* po = g_po + ((size_t)(split * BB + b) * NP + row0 + wr) * CI;
    float* pm = g_pm + (size_t)(split * BB + b) * NP + row0 + wr;
    float* pl = g_pl + (size_t)(split * BB + b) * NP + row0 + wr;
#pragma unroll
    for (int mf = 0; mf < 2; mf++) {
        int r0 = mf * 16 + g;
#pragma unroll
        for (int nf = 0; nf < 16; nf++) {
            *(float2*)&po[(size_t)r0 * CI + nf * 8 + c2] =
                make_float2(o[mf][nf][0], o[mf][nf][1]);
            *(float2*)&po[(size_t)(r0 + 8) * CI + nf * 8 + c2] =
                make_float2(o[mf][nf][2], o[mf][nf][3]);
        }
        if ((lane & 3) == 0) {
            pm[r0] = mrun[mf][0]; pm[r0 + 8] = mrun[mf][1];
            pl[r0] = lrun[mf][0]; pl[r0 + 8] = lrun[mf][1];
        }
    }
}

// =================================================================
// Kernel 3: fused merge + output projection, 128n x 64c tiles,
// 4 CTAs/SM for latency hiding. 3-pass hi/lo (same math as R8).
// smem: A_hi 0..16K | A_lo 16..32K | W_hi 32..40K | W_lo 40..48K
// =================================================================
#define OP_SMEM 49152

__global__ __launch_bounds__(256, 4) void outproj_kernel(
    const float* __restrict__ x, const float* __restrict__ wb,
    float* __restrict__ out)
{
    extern __shared__ char ps[];
    __shared__ float wgt0[128], wgt1[128];
    const u32 s32 = smem_u32(ps);
    const int b  = blockIdx.z;
    const int cb = blockIdx.y * 64;
    const int n0 = blockIdx.x * 128;
    const int t  = threadIdx.x;
    const int lane = t & 31;
    const int w  = t >> 5;
    const int wm = w & 3;         // n-subtile (32 rows)
    const int wn = w >> 2;        // c-subtile (32 cols)
    const int lrow = lane & 15;
    const int lcol = (lane >> 4) * 16;
    const int g    = lane >> 2;
    const int c2   = (lane & 3) * 2;

    if (t < 128) {
        int bn = b * NP + n0 + t;
        float m0 = g_pm[bn], m1 = g_pm[BB * NP + bn];
        float l0 = g_pl[bn], l1 = g_pl[BB * NP + bn];
        float m  = fmaxf(m0, m1);
        float w0 = ex2(m0 - m), w1 = ex2(m1 - m);
        float inv = 1.0f / (w0 * l0 + w1 * l1);
        wgt0[t] = w0 * inv;
        wgt1[t] = w1 * inv;
    }
    __syncthreads();

    float acc[2][4][4];
#pragma unroll
    for (int mf = 0; mf < 2; mf++)
#pragma unroll
        for (int nf = 0; nf < 4; nf++)
#pragma unroll
            for (int q = 0; q < 4; q++) acc[mf][nf][q] = 0.0f;

    const float* p0 = g_po + ((size_t)b * NP + n0) * CI;
    const float* p1 = g_po + ((size_t)(BB + b) * NP + n0) * CI;

    for (int o0 = 0; o0 < CI; o0 += 64) {
        __syncthreads();
        // stage merged A [128n][64o] hi/lo
#pragma unroll
        for (int i = 0; i < 8; i++) {
            int id = i * 256 + t;
            int row = id >> 4, ch = id & 15;
            float4 a = *(const float4*)&p0[(size_t)row * CI + o0 + ch * 4];
            float4 c = *(const float4*)&p1[(size_t)row * CI + o0 + ch * 4];
            float w0 = wgt0[row], w1 = wgt1[row];
            float m[4] = {a.x * w0 + c.x * w1, a.y * w0 + c.y * w1,
                          a.z * w0 + c.z * w1, a.w * w0 + c.w * w1};
            __half h[4], l[4];
#pragma unroll
            for (int q = 0; q < 4; q++) {
                h[q] = __float2half_rn(m[q]);
                l[q] = __float2half_rn(m[q] - __half2float(h[q]));
            }
            u32 sw = SWZ128(row * 128 + ch * 8);
            *(uint2*)(ps + sw)         = make_uint2(h2u(h[0], h[1]), h2u(h[2], h[3]));
            *(uint2*)(ps + 16384 + sw) = make_uint2(h2u(l[0], l[1]), h2u(l[2], l[3]));
        }
        // stage W [64c][64o] hi/lo
#pragma unroll
        for (int i = 0; i < 2; i++) {
            int id = i * 256 + t;
            int row = id >> 3, ch = id & 7;
            u32 sw = SWZ128(row * 128 + ch * 16);
            cpa(s32 + 32768 + sw, g_wwh + (size_t)(cb + row) * CI + o0 + ch * 8);
            cpa(s32 + 40960 + sw, g_wwl + (size_t)(cb + row) * CI + o0 + ch * 8);
        }
        CP_COMMIT();
        CP_WAIT0();
        __syncthreads();

#pragma unroll
        for (int kc = 0; kc < 4; kc++) {
            u32 Ah[2][4], Al[2][4], B[2][4];
#pragma unroll
            for (int mf = 0; mf < 2; mf++)
                ldm4(Ah[mf][0], Ah[mf][1], Ah[mf][2], Ah[mf][3],
                     s32 + SWZ128((wm * 32 + mf * 16 + lrow) * 128 + kc * 32 + lcol));
#pragma unroll
            for (int bf = 0; bf < 2; bf++)
                ldm4(B[bf][0], B[bf][1], B[bf][2], B[bf][3],
                     s32 + 32768 + SWZ128((wn * 32 + bf * 16 + lrow) * 128 + kc * 32 + lcol));
#pragma unroll
            for (int mf = 0; mf < 2; mf++)
#pragma unroll
                for (int bf = 0; bf < 2; bf++) {
                    mma16816(acc[mf][2 * bf],     Ah[mf][0], Ah[mf][1], Ah[mf][2], Ah[mf][3], B[bf][0], B[bf][2]);
                    mma16816(acc[mf][2 * bf + 1], Ah[mf][0], Ah[mf][1], Ah[mf][2], Ah[mf][3], B[bf][1], B[bf][3]);
                }
#pragma unroll
            for (int mf = 0; mf < 2; mf++)
                ldm4(Al[mf][0], Al[mf][1], Al[mf][2], Al[mf][3],
                     s32 + 16384 + SWZ128((wm * 32 + mf * 16 + lrow) * 128 + kc * 32 + lcol));
#pragma unroll
            for (int mf = 0; mf < 2; mf++)
#pragma unroll
                for (int bf = 0; bf < 2; bf++) {
                    mma16816(acc[mf][2 * bf],     Al[mf][0], Al[mf][1], Al[mf][2], Al[mf][3], B[bf][0], B[bf][2]);
                    mma16816(acc[mf][2 * bf + 1], Al[mf][0], Al[mf][1], Al[mf][2], Al[mf][3], B[bf][1], B[bf][3]);
                }
#pragma unroll
            for (int bf = 0; bf < 2; bf++)
                ldm4(B[bf][0], B[bf][1], B[bf][2], B[bf][3],
                     s32 + 40960 + SWZ128((wn * 32 + bf * 16 + lrow) * 128 + kc * 32 + lcol));
#pragma unroll
            for (int mf = 0; mf < 2; mf++)
#pragma unroll
                for (int bf = 0; bf < 2; bf++) {
                    mma16816(acc[mf][2 * bf],     Ah[mf][0], Ah[mf][1], Ah[mf][2], Ah[mf][3], B[bf][0], B[bf][2]);
                    mma16816(acc[mf][2 * bf + 1], Ah[mf][0], Ah[mf][1], Ah[mf][2], Ah[mf][3], B[bf][1], B[bf][3]);
                }
        }
    }
    __syncthreads();

    // stage D as [64c][128n] f32 (32KB, reuses A region)
#pragma unroll
    for (int mf = 0; mf < 2; mf++) {
        int nl = wm * 32 + mf * 16 + g;
#pragma unroll
        for (int nf = 0; nf < 4; nf++) {
            int cl = wn * 32 + nf * 8 + c2;
            *(float*)(ps + (cl * 128 + nl) * 4)           = acc[mf][nf][0];
            *(float*)(ps + ((cl + 1) * 128 + nl) * 4)     = acc[mf][nf][1];
            *(float*)(ps + (cl * 128 + nl + 8) * 4)       = acc[mf][nf][2];
            *(float*)(ps + ((cl + 1) * 128 + nl + 8) * 4) = acc[mf][nf][3];
        }
    }
    __syncthreads();

    int r = t >> 2, part = t & 3;
    float bv = wb[cb + r];
    size_t base = ((size_t)b * CC + cb + r) * NP + n0 + part * 32;
#pragma unroll
    for (int k = 0; k < 8; k++) {
        float4 v  = *(float4*)(ps + (r * 128 + part * 32 + k * 4) * 4);
        float4 xv = *(const float4*)&x[base + k * 4];
        float4 rr = make_float4(v.x + bv + xv.x, v.y + bv + xv.y,
                                v.z + bv + xv.z, v.w + bv + xv.w);
        *(float4*)&out[base + k * 4] = rr;
    }
}

// =================================================================
extern "C" void kernel_launch(void* const* d_in, const int* in_sizes, int n_in,
                              void* d_out, int out_size)
{
    const float* x  = (const float*)d_in[0];
    const float* tw = (const float*)d_in[1];
    const float* tb = (const float*)d_in[2];
    const float* pw = (const float*)d_in[3];
    const float* pb = (const float*)d_in[4];
    const float* gw = (const float*)d_in[5];
    const float* gb = (const float*)d_in[6];
    const float* ww = (const float*)d_in[7];
    const float* wb = (const float*)d_in[8];
    float* out = (float*)d_out;

    cudaFuncSetAttribute(attn_kernel,    cudaFuncAttributeMaxDynamicSharedMemorySize, SMEM_ATTN);
    cudaFuncSetAttribute(proj_kernel,    cudaFuncAttributeMaxDynamicSharedMemorySize, PJX_SMEM);
    cudaFuncSetAttribute(outproj_kernel, cudaFuncAttributeMaxDynamicSharedMemorySize, OP_SMEM);

    conv_all<<<4096 + 128, 256>>>(x, tw, pw, gw, ww);
    proj_kernel<<<dim3(NP / 128, BB), 256, PJX_SMEM>>>(tb, pb, gb);
    attn_kernel<<<dim3(NP / 128, 2, BB), 128, SMEM_ATTN>>>();
    outproj_kernel<<<dim3(NP / 128, CC / 64, BB), 256, OP_SMEM>>>(x, wb, out);
}

// round 12
// speedup vs baseline: 1.0050x; 1.0050x over previous
#include <cuda_runtime.h>
#include <cuda_fp16.h>
#include <math.h>
#include <stdint.h>

#define BB 4
#define CC 256
#define CI 128
#define NP 4096
#define LOG2E 1.4426950408889634f

typedef unsigned long long u64;
typedef unsigned int u32;

// Scratch (device globals: allocation-free rule)
__device__ __half g_xh[BB * CC * NP];  // x hi : (b, c, n)
__device__ __half g_xl[BB * CC * NP];  // x lo
__device__ __half g_twh[CI * CC], g_twl[CI * CC];
__device__ __half g_pwh[CI * CC], g_pwl[CI * CC];
__device__ __half g_gwh[CI * CC], g_gwl[CI * CC];
__device__ __half g_wwh[CC * CI], g_wwl[CC * CI];
__device__ __half g_qh[BB * NP * CI];  // theta(x)*log2e hi         : (b, n, o)
__device__ __half g_qc[BB * NP * CI];  // qh/64 + ql (correction)   : (b, n, o)
__device__ __half g_kh[BB * NP * CI];  // phi(x) hi                 : (b, m, o)
__device__ __half g_kc[BB * NP * CI];  // kh + 64*kl (correction)   : (b, m, o)
__device__ __half g_vt[BB * CI * NP];  // g(x) transposed           : (b, o, m)
__device__ float  g_po[2 * BB * NP * CI];  // unnormalized partial O per kv-split
__device__ float  g_pm[2 * BB * NP];       // partial running max (log2 domain)
__device__ float  g_pl[2 * BB * NP];       // partial running sum

// ---------------- helpers ----------------
__device__ __forceinline__ float ex2(float x) {
    float y;
    asm("ex2.approx.ftz.f32 %0, %1;" : "=f"(y) : "f"(x));
    return y;
}
__device__ __forceinline__ u32 smem_u32(const void* p) {
    u32 a;
    asm("{ .reg .u64 t; cvta.to.shared.u64 t, %1; cvt.u32.u64 %0, t; }" : "=r"(a) : "l"(p));
    return a;
}
__device__ __forceinline__ u32 h2u(__half a, __half b) {
    __half2 h = __halves2half2(a, b);
    return *(u32*)&h;
}

// ---------------- mma.sync / ldmatrix / cp.async ----------------
__device__ __forceinline__ void ldm4(u32& r0, u32& r1, u32& r2, u32& r3, u32 addr) {
    asm volatile("ldmatrix.sync.aligned.m8n8.x4.shared.b16 {%0,%1,%2,%3}, [%4];"
                 : "=r"(r0), "=r"(r1), "=r"(r2), "=r"(r3) : "r"(addr));
}
__device__ __forceinline__ void ldm4t(u32& r0, u32& r1, u32& r2, u32& r3, u32 addr) {
    asm volatile("ldmatrix.sync.aligned.m8n8.x4.trans.shared.b16 {%0,%1,%2,%3}, [%4];"
                 : "=r"(r0), "=r"(r1), "=r"(r2), "=r"(r3) : "r"(addr));
}
__device__ __forceinline__ void mma16816(float* c, u32 a0, u32 a1, u32 a2, u32 a3,
                                         u32 b0, u32 b1) {
    asm volatile(
        "mma.sync.aligned.m16n8k16.row.col.f32.f16.f16.f32 "
        "{%0,%1,%2,%3}, {%4,%5,%6,%7}, {%8,%9}, {%0,%1,%2,%3};"
        : "+f"(c[0]), "+f"(c[1]), "+f"(c[2]), "+f"(c[3])
        : "r"(a0), "r"(a1), "r"(a2), "r"(a3), "r"(b0), "r"(b1));
}
__device__ __forceinline__ void cpa(u32 s, const void* g) {
    asm volatile("cp.async.cg.shared.global [%0], [%1], 16;" :: "r"(s), "l"(g));
}
#define CP_COMMIT() asm volatile("cp.async.commit_group;")
#define CP_WAIT1()  asm volatile("cp.async.wait_group 1;")
#define CP_WAIT0()  asm volatile("cp.async.wait_group 0;")

#define SWZ256(x) ((x) ^ (((x) >> 4) & 0x70))   // 256B rows
#define SWZ128(x) ((x) ^ (((x) >> 3) & 0x70))   // 128B rows

#define HONE 0x3C003C00u   // half2(1.0, 1.0)

// =================================================================
// Kernel 0: fp32 -> fp16 hi/lo conversion, single launch for x + 4 weights.
// =================================================================
__global__ __launch_bounds__(256) void conv_all(
    const float* __restrict__ x,
    const float* __restrict__ tw, const float* __restrict__ pw,
    const float* __restrict__ gw, const float* __restrict__ ww)
{
    int bid = blockIdx.x;
    const float* src;
    __half *dh, *dl;
    int i;
    if (bid < 4096) {
        src = x; dh = g_xh; dl = g_xl;
        i = bid * 1024 + threadIdx.x * 4;
    } else {
        int wsel = (bid - 4096) >> 5;
        i = ((bid - 4096) & 31) * 1024 + threadIdx.x * 4;
        src = (wsel == 0) ? tw : (wsel == 1) ? pw : (wsel == 2) ? gw : ww;
        dh  = (wsel == 0) ? g_twh : (wsel == 1) ? g_pwh : (wsel == 2) ? g_gwh : g_wwh;
        dl  = (wsel == 0) ? g_twl : (wsel == 1) ? g_pwl : (wsel == 2) ? g_gwl : g_wwl;
    }
    float4 v = *(const float4*)&src[i];
    __half h0 = __float2half_rn(v.x), h1 = __float2half_rn(v.y);
    __half h2 = __float2half_rn(v.z), h3 = __float2half_rn(v.w);
    __half l0 = __float2half_rn(v.x - __half2float(h0));
    __half l1 = __float2half_rn(v.y - __half2float(h1));
    __half l2 = __float2half_rn(v.z - __half2float(h2));
    __half l3 = __float2half_rn(v.w - __half2float(h3));
    *(uint2*)&dh[i] = make_uint2(h2u(h0, h1), h2u(h2, h3));
    *(uint2*)&dl[i] = make_uint2(h2u(l0, l1), h2u(l2, l3));
}

// =================================================================
// Kernel 1: QKV projections, X-resident mega kernel (R10, unchanged).
// =================================================================
#define PJX_XH   0
#define PJX_XL   65536
#define PJX_W0   131072
#define PJX_W1   163840
#define PJX_SMEM 196608

__device__ __forceinline__ void stage_w(u32 wbase, const __half* Wh,
                                        const __half* Wl, int c0, int t)
{
#pragma unroll
    for (int i = 0; i < 4; i++) {
        int id = i * 256 + t;
        int row = id >> 3, ch = id & 7;
        u32 sw = SWZ128(row * 128 + ch * 16);
        cpa(wbase + sw,         Wh + (size_t)row * CC + c0 + ch * 8);
        cpa(wbase + 16384 + sw, Wl + (size_t)row * CC + c0 + ch * 8);
    }
}

__global__ __launch_bounds__(256, 1) void proj_kernel(
    const float* __restrict__ tb, const float* __restrict__ pb,
    const float* __restrict__ gb)
{
    extern __shared__ char ps[];
    __shared__ float bias_s[3][128];
    const u32 s32 = smem_u32(ps);
    const int b  = blockIdx.y;
    const int n0 = blockIdx.x * 128;
    const int t  = threadIdx.x;
    const int lane = t & 31;
    const int w  = t >> 5;
    const int wm = w & 3;
    const int wn = w >> 2;

    const int lrow = lane & 15;
    const int lcol = (lane >> 4) * 16;
    const int g    = lane >> 2;
    const int c2   = (lane & 3) * 2;
    const int trow = ((lane >> 4) << 3) + (lane & 7);
    const int tcol = ((lane >> 3) & 1) * 8;

    const __half* WH[3] = {g_twh, g_pwh, g_gwh};
    const __half* WL[3] = {g_twl, g_pwl, g_gwl};
    const __half* Xh = g_xh + (size_t)b * CC * NP;
    const __half* Xl = g_xl + (size_t)b * CC * NP;

    if (t < 128) {
        bias_s[0][t] = tb[t];
        bias_s[1][t] = pb[t];
        bias_s[2][t] = gb[t];
    }

    // ---- prologue: stage X (once) + W chunks 0,1 ----
#pragma unroll
    for (int i = 0; i < 16; i++) {
        int id = i * 256 + t;
        int row = id >> 4, ch = id & 15;
        u32 sw = SWZ256(row * 256 + ch * 16);
        cpa(s32 + PJX_XH + sw, Xh + (size_t)row * NP + n0 + ch * 8);
        cpa(s32 + PJX_XL + sw, Xl + (size_t)row * NP + n0 + ch * 8);
    }
    stage_w(s32 + PJX_W0, WH[0], WL[0], 0, t);
    CP_COMMIT();
    stage_w(s32 + PJX_W1, WH[0], WL[0], 64, t);
    CP_COMMIT();

    float acc[2][8][4];

    for (int q = 0; q < 12; q++) {
        const int z  = q >> 2;
        const int c0 = (q & 3) * 64;
        const u32 wb = s32 + ((q & 1) ? PJX_W1 : PJX_W0);

        if ((q & 3) == 0) {
#pragma unroll
            for (int mf = 0; mf < 2; mf++)
#pragma unroll
                for (int nf = 0; nf < 8; nf++)
#pragma unroll
                    for (int p = 0; p < 4; p++) acc[mf][nf][p] = 0.0f;
        }

        CP_WAIT1();
        __syncthreads();

#pragma unroll
        for (int kc = 0; kc < 4; kc++) {
            u32 Ah[2][4], Al[2][4], B[4][4];
#pragma unroll
            for (int mf = 0; mf < 2; mf++)
                ldm4t(Ah[mf][0], Ah[mf][1], Ah[mf][2], Ah[mf][3],
                      s32 + PJX_XH + SWZ256((c0 + kc * 16 + trow) * 256 + (wm * 32 + mf * 16 + tcol) * 2));
#pragma unroll
            for (int bf = 0; bf < 4; bf++)
                ldm4(B[bf][0], B[bf][1], B[bf][2], B[bf][3],
                     wb + SWZ128((wn * 64 + bf * 16 + lrow) * 128 + kc * 32 + lcol));
#pragma unroll
            for (int mf = 0; mf < 2; mf++)
#pragma unroll
                for (int bf = 0; bf < 4; bf++) {
                    mma16816(acc[mf][2 * bf],     Ah[mf][0], Ah[mf][1], Ah[mf][2], Ah[mf][3], B[bf][0], B[bf][2]);
                    mma16816(acc[mf][2 * bf + 1], Ah[mf][0], Ah[mf][1], Ah[mf][2], Ah[mf][3], B[bf][1], B[bf][3]);
                }
#pragma unroll
            for (int mf = 0; mf < 2; mf++)
                ldm4t(Al[mf][0], Al[mf][1], Al[mf][2], Al[mf][3],
                      s32 + PJX_XL + SWZ256((c0 + kc * 16 + trow) * 256 + (wm * 32 + mf * 16 + tcol) * 2));
#pragma unroll
            for (int mf = 0; mf < 2; mf++)
#pragma unroll
                for (int bf = 0; bf < 4; bf++) {
                    mma16816(acc[mf][2 * bf],     Al[mf][0], Al[mf][1], Al[mf][2], Al[mf][3], B[bf][0], B[bf][2]);
                    mma16816(acc[mf][2 * bf + 1], Al[mf][0], Al[mf][1], Al[mf][2], Al[mf][3], B[bf][1], B[bf][3]);
                }
#pragma unroll
            for (int bf = 0; bf < 4; bf++)
                ldm4(B[bf][0], B[bf][1], B[bf][2], B[bf][3],
                     wb + 16384 + SWZ128((wn * 64 + bf * 16 + lrow) * 128 + kc * 32 + lcol));
#pragma unroll
            for (int mf = 0; mf < 2; mf++)
#pragma unroll
                for (int bf = 0; bf < 4; bf++) {
                    mma16816(acc[mf][2 * bf],     Ah[mf][0], Ah[mf][1], Ah[mf][2], Ah[mf][3], B[bf][0], B[bf][2]);
                    mma16816(acc[mf][2 * bf + 1], Ah[mf][0], Ah[mf][1], Ah[mf][2], Ah[mf][3], B[bf][1], B[bf][3]);
                }
        }

        __syncthreads();
        if (q + 2 < 12) {
            int q2 = q + 2;
            stage_w(s32 + ((q2 & 1) ? PJX_W1 : PJX_W0),
                    WH[q2 >> 2], WL[q2 >> 2], (q2 & 3) * 64, t);
        }
        CP_COMMIT();

        if ((q & 3) == 3) {
            if (z == 2) {
#pragma unroll
                for (int mf = 0; mf < 2; mf++) {
                    int nl = wm * 32 + mf * 16 + g;
#pragma unroll
                    for (int nf = 0; nf < 8; nf++) {
                        int o = wn * 64 + nf * 8 + c2;
                        __half h00 = __float2half_rn(acc[mf][nf][0] + bias_s[2][o]);
                        __half h01 = __float2half_rn(acc[mf][nf][1] + bias_s[2][o + 1]);
                        __half h10 = __float2half_rn(acc[mf][nf][2] + bias_s[2][o]);
                        __half h11 = __float2half_rn(acc[mf][nf][3] + bias_s[2][o + 1]);
                        *(__half*)(ps + (o * 128 + nl) * 2)           = h00;
                        *(__half*)(ps + ((o + 1) * 128 + nl) * 2)     = h01;
                        *(__half*)(ps + (o * 128 + nl + 8) * 2)       = h10;
                        *(__half*)(ps + ((o + 1) * 128 + nl + 8) * 2) = h11;
                    }
                }
                __syncthreads();
                int o = t >> 1, part = t & 1;
                __half* dst = g_vt + ((size_t)b * CI + o) * NP + n0 + part * 64;
#pragma unroll
                for (int k = 0; k < 8; k++)
                    *(uint4*)&dst[k * 8] = *(uint4*)(ps + (o * 128 + part * 64 + k * 8) * 2);
            } else {
                __half* dh = (z == 0) ? g_qh : g_kh;
                __half* dc = (z == 0) ? g_qc : g_kc;
                const float sc = (z == 0) ? LOG2E : 1.0f;
                const size_t bq = (size_t)b * NP + n0;
#pragma unroll
                for (int mf = 0; mf < 2; mf++) {
                    int nl = wm * 32 + mf * 16 + g;
#pragma unroll
                    for (int nf = 0; nf < 8; nf++) {
                        int o = wn * 64 + nf * 8 + c2;
                        float bv0 = bias_s[z][o], bv1 = bias_s[z][o + 1];
                        float v[4];
                        v[0] = (acc[mf][nf][0] + bv0) * sc;
                        v[1] = (acc[mf][nf][1] + bv1) * sc;
                        v[2] = (acc[mf][nf][2] + bv0) * sc;
                        v[3] = (acc[mf][nf][3] + bv1) * sc;
                        __half hh[4], cc[4];
#pragma unroll
                        for (int p = 0; p < 4; p++) {
                            __half h = __float2half_rn(v[p]);
                            float  hf = __half2float(h);
                            float  l  = v[p] - hf;
                            hh[p] = h;
                            cc[p] = (z == 0) ? __float2half_rn(hf * 0.015625f + l)
                                             : __float2half_rn(hf + 64.0f * l);
                        }
                        size_t i0 = (bq + nl) * CI + o;
                        size_t i1 = i0 + (size_t)8 * CI;
                        *(u32*)&dh[i0] = h2u(hh[0], hh[1]);
                        *(u32*)&dc[i0] = h2u(cc[0], cc[1]);
                        *(u32*)&dh[i1] = h2u(hh[2], hh[3]);
                        *(u32*)&dc[i1] = h2u(cc[2], cc[3]);
                    }
                }
            }
        }
    }
}

// =================================================================
// Kernel 2: flash attention, 128 threads/CTA (4 warps x 32 q-rows),
// 2-pass QK^T, KV-split 2, swizzled smem, 2 CTAs/SM.
// exp via h2exp2 (halved MUFU); l via ones-MMA.
// =================================================================
#define OFF_QH 0
#define OFF_QC 32768
#define OFF_KH 65536
#define OFF_KC 81920
#define OFF_V  98304
#define SMEM_ATTN 114688
#define KV_TILES 32

__device__ __forceinline__ void load_k(u32 s32, int m0,
                                       const __half* gkh, const __half* gkc, int t)
{
#pragma unroll
    for (int i = 0; i < 8; i++) {
        int id = i * 128 + t;
        int row = id >> 4, c = id & 15;
        u32 sw = SWZ256(row * 256 + c * 16);
        cpa(s32 + OFF_KH + sw, gkh + (size_t)(m0 + row) * CI + c * 8);
        cpa(s32 + OFF_KC + sw, gkc + (size_t)(m0 + row) * CI + c * 8);
    }
}
__device__ __forceinline__ void load_v(u32 s32, int m0, const __half* gvt, int t)
{
#pragma unroll
    for (int i = 0; i < 8; i++) {
        int id = i * 128 + t;
        int row = id >> 3, c = id & 7;
        cpa(s32 + OFF_V + SWZ128(row * 128 + c * 16), gvt + (size_t)row * NP + m0 + c * 8);
    }
}

__global__ __launch_bounds__(128, 2) void attn_kernel()
{
    extern __shared__ __align__(128) char smem[];
    const u32 s32   = smem_u32(smem);
    const int t     = threadIdx.x;
    const int lane  = t & 31;
    const int wr    = (t >> 5) * 32;
    const int row0  = blockIdx.x * 128;
    const int split = blockIdx.y;
    const int b     = blockIdx.z;
    const int kv0   = split * (NP / 2);

    const int lrow = lane & 15;
    const int lcol = (lane >> 4) * 16;
    const int g    = lane >> 2;
    const int c2   = (lane & 3) * 2;

    const __half* gqh = g_qh + ((size_t)b * NP + row0) * CI;
    const __half* gqc = g_qc + ((size_t)b * NP + row0) * CI;
    const __half* gkh = g_kh + ((size_t)b * NP + kv0) * CI;
    const __half* gkc = g_kc + ((size_t)b * NP + kv0) * CI;
    const __half* gvt = g_vt + (size_t)b * CI * NP + kv0;

#pragma unroll
    for (int i = 0; i < 16; i++) {
        int id = i * 128 + t;
        int row = id >> 4, c = id & 15;
        u32 sw = SWZ256(row * 256 + c * 16);
        cpa(s32 + OFF_QH + sw, gqh + (size_t)row * CI + c * 8);
        cpa(s32 + OFF_QC + sw, gqc + (size_t)row * CI + c * 8);
    }
    load_k(s32, 0, gkh, gkc, t);
    CP_COMMIT();
    load_v(s32, 0, gvt, t);
    CP_COMMIT();

    float o[2][16][4];
#pragma unroll
    for (int mf = 0; mf < 2; mf++)
#pragma unroll
        for (int nf = 0; nf < 16; nf++)
#pragma unroll
            for (int q = 0; q < 4; q++) o[mf][nf][q] = 0.0f;
    float mrun[2][2] = {{-1e30f, -1e30f}, {-1e30f, -1e30f}};
    float lrun[2][2] = {{0.0f, 0.0f}, {0.0f, 0.0f}};

    for (int tile = 0; tile < KV_TILES; tile++) {
        CP_WAIT1();
        __syncthreads();

        float s[2][8][4];
#pragma unroll
        for (int mf = 0; mf < 2; mf++)
#pragma unroll
            for (int nf = 0; nf < 8; nf++)
#pragma unroll
                for (int q = 0; q < 4; q++) s[mf][nf][q] = 0.0f;

#pragma unroll
        for (int kc = 0; kc < 8; kc++) {
            u32 qa[2][4];
#pragma unroll
            for (int mf = 0; mf < 2; mf++)
                ldm4(qa[mf][0], qa[mf][1], qa[mf][2], qa[mf][3],
                     s32 + OFF_QH + SWZ256((wr + mf * 16 + lrow) * 256 + kc * 32 + lcol));
#pragma unroll
            for (int nb = 0; nb < 4; nb++) {
                u32 k0, k1, k2, k3;
                ldm4(k0, k1, k2, k3,
                     s32 + OFF_KH + SWZ256((nb * 16 + lrow) * 256 + kc * 32 + lcol));
#pragma unroll
                for (int mf = 0; mf < 2; mf++) {
                    mma16816(s[mf][2 * nb],     qa[mf][0], qa[mf][1], qa[mf][2], qa[mf][3], k0, k2);
                    mma16816(s[mf][2 * nb + 1], qa[mf][0], qa[mf][1], qa[mf][2], qa[mf][3], k1, k3);
                }
            }
        }
#pragma unroll
        for (int mf = 0; mf < 2; mf++)
#pragma unroll
            for (int nf = 0; nf < 8; nf++)
#pragma unroll
                for (int q = 0; q < 4; q++) s[mf][nf][q] *= 0.984375f;

#pragma unroll
        for (int kc = 0; kc < 8; kc++) {
            u32 qa[2][4];
#pragma unroll
            for (int mf = 0; mf < 2; mf++)
                ldm4(qa[mf][0], qa[mf][1], qa[mf][2], qa[mf][3],
                     s32 + OFF_QC + SWZ256((wr + mf * 16 + lrow) * 256 + kc * 32 + lcol));
#pragma unroll
            for (int nb = 0; nb < 4; nb++) {
                u32 k0, k1, k2, k3;
                ldm4(k0, k1, k2, k3,
                     s32 + OFF_KC + SWZ256((nb * 16 + lrow) * 256 + kc * 32 + lcol));
#pragma unroll
                for (int mf = 0; mf < 2; mf++) {
                    mma16816(s[mf][2 * nb],     qa[mf][0], qa[mf][1], qa[mf][2], qa[mf][3], k0, k2);
                    mma16816(s[mf][2 * nb + 1], qa[mf][0], qa[mf][1], qa[mf][2], qa[mf][3], k1, k3);
                }
            }
        }

        __syncthreads();
        if (tile + 1 < KV_TILES) load_k(s32, (tile + 1) * 64, gkh, gkc, t);
        CP_COMMIT();

        // ---- online softmax (fp16x2 exp; l via ones-MMA) ----
        float corr[2][2];
        u32   p[2][4][4];
#pragma unroll
        for (int mf = 0; mf < 2; mf++) {
            float mx0 = fmaxf(s[mf][0][0], s[mf][0][1]);
            float mx1 = fmaxf(s[mf][0][2], s[mf][0][3]);
#pragma unroll
            for (int nf = 1; nf < 8; nf++) {
                mx0 = fmaxf(mx0, fmaxf(s[mf][nf][0], s[mf][nf][1]));
                mx1 = fmaxf(mx1, fmaxf(s[mf][nf][2], s[mf][nf][3]));
            }
            mx0 = fmaxf(mx0, __shfl_xor_sync(0xffffffffu, mx0, 1));
            mx0 = fmaxf(mx0, __shfl_xor_sync(0xffffffffu, mx0, 2));
            mx1 = fmaxf(mx1, __shfl_xor_sync(0xffffffffu, mx1, 1));
            mx1 = fmaxf(mx1, __shfl_xor_sync(0xffffffffu, mx1, 2));
            float mnew0 = fmaxf(mrun[mf][0], mx0);
            float mnew1 = fmaxf(mrun[mf][1], mx1);
            corr[mf][0] = ex2(mrun[mf][0] - mnew0);
            corr[mf][1] = ex2(mrun[mf][1] - mnew1);
            mrun[mf][0] = mnew0;
            mrun[mf][1] = mnew1;

#pragma unroll
            for (int kc2 = 0; kc2 < 4; kc2++) {
#pragma unroll
                for (int half = 0; half < 2; half++) {
                    int nf = 2 * kc2 + half;
                    __half2 e01 = h2exp2(__floats2half2_rn(s[mf][nf][0] - mnew0,
                                                           s[mf][nf][1] - mnew0));
                    __half2 e23 = h2exp2(__floats2half2_rn(s[mf][nf][2] - mnew1,
                                                           s[mf][nf][3] - mnew1));
                    p[mf][kc2][2 * half]     = *(u32*)&e01;
                    p[mf][kc2][2 * half + 1] = *(u32*)&e23;
                }
            }
        }

        // l_tile = P . 1  (8 HMMA, no LDS, no shuffles)
        float lc[2][4] = {{0.0f, 0.0f, 0.0f, 0.0f}, {0.0f, 0.0f, 0.0f, 0.0f}};
#pragma unroll
        for (int mf = 0; mf < 2; mf++)
#pragma unroll
            for (int kc2 = 0; kc2 < 4; kc2++)
                mma16816(lc[mf], p[mf][kc2][0], p[mf][kc2][1],
                         p[mf][kc2][2], p[mf][kc2][3], HONE, HONE);
#pragma unroll
        for (int mf = 0; mf < 2; mf++) {
            lrun[mf][0] = lrun[mf][0] * corr[mf][0] + lc[mf][0];
            lrun[mf][1] = lrun[mf][1] * corr[mf][1] + lc[mf][2];
        }

        if (__any_sync(0xffffffffu,
                       fminf(fminf(corr[0][0], corr[0][1]),
                             fminf(corr[1][0], corr[1][1])) < 0.99999f)) {
#pragma unroll
            for (int mf = 0; mf < 2; mf++)
#pragma unroll
                for (int nf = 0; nf < 16; nf++) {
                    o[mf][nf][0] *= corr[mf][0]; o[mf][nf][1] *= corr[mf][0];
                    o[mf][nf][2] *= corr[mf][1]; o[mf][nf][3] *= corr[mf][1];
                }
        }

        CP_WAIT1();
        __syncthreads();

#pragma unroll
        for (int kc2 = 0; kc2 < 4; kc2++) {
#pragma unroll
            for (int dg = 0; dg < 8; dg++) {
                u32 v0, v1, v2, v3;
                ldm4(v0, v1, v2, v3,
                     s32 + OFF_V + SWZ128((dg * 16 + lrow) * 128 + kc2 * 32 + lcol));
#pragma unroll
                for (int mf = 0; mf < 2; mf++) {
                    mma16816(o[mf][2 * dg],
                             p[mf][kc2][0], p[mf][kc2][1], p[mf][kc2][2], p[mf][kc2][3], v0, v2);
                    mma16816(o[mf][2 * dg + 1],
                             p[mf][kc2][0], p[mf][kc2][1], p[mf][kc2][2], p[mf][kc2][3], v1, v3);
                }
            }
        }

        __syncthreads();
        if (tile + 1 < KV_TILES) load_v(s32, (tile + 1) * 64, gvt, t);
        CP_COMMIT();
    }

    float* po = g_po + ((size_t)(split * BB + b) * NP + row0 + wr) * CI;
    float* pm = g_pm + (size_t)(split * BB + b) * NP + row0 + wr;
    float* pl = g_pl + (size_t)(split * BB + b) * NP + row0 + wr;
#pragma unroll
    for (int mf = 0; mf < 2; mf++) {
        int r0 = mf * 16 + g;
#pragma unroll
        for (int nf = 0; nf < 16; nf++) {
            *(float2*)&po[(size_t)r0 * CI + nf * 8 + c2] =
                make_float2(o[mf][nf][0], o[mf][nf][1]);
            *(float2*)&po[(size_t)(r0 + 8) * CI + nf * 8 + c2] =
                make_float2(o[mf][nf][2], o[mf][nf][3]);
        }
        if ((lane & 3) == 0) {
            pm[r0] = mrun[mf][0]; pm[r0 + 8] = mrun[mf][1];
            pl[r0] = lrun[mf][0]; pl[r0 + 8] = lrun[mf][1];
        }
    }
}

// =================================================================
// Kernel 3: fused merge + output projection (exact R8 version).
// =================================================================
#define OP_SMEM 65536

__global__ __launch_bounds__(256, 2) void outproj_kernel(
    const float* __restrict__ x, const float* __restrict__ wb,
    float* __restrict__ out)
{
    extern __shared__ char ps[];
    __shared__ float wgt0[128], wgt1[128];
    const u32 s32 = smem_u32(ps);
    const int b  = blockIdx.z;
    const int cb = blockIdx.y * 128;
    const int n0 = blockIdx.x * 128;
    const int t  = threadIdx.x;
    const int lane = t & 31;
    const int w  = t >> 5;
    const int wm = w & 3;
    const int wn = w >> 2;
    const int lrow = lane & 15;
    const int lcol = (lane >> 4) * 16;
    const int g    = lane >> 2;
    const int c2   = (lane & 3) * 2;

    if (t < 128) {
        int bn = b * NP + n0 + t;
        float m0 = g_pm[bn], m1 = g_pm[BB * NP + bn];
        float l0 = g_pl[bn], l1 = g_pl[BB * NP + bn];
        float m  = fmaxf(m0, m1);
        float w0 = ex2(m0 - m), w1 = ex2(m1 - m);
        float inv = 1.0f / (w0 * l0 + w1 * l1);
        wgt0[t] = w0 * inv;
        wgt1[t] = w1 * inv;
    }
    __syncthreads();

    float acc[2][8][4];
#pragma unroll
    for (int mf = 0; mf < 2; mf++)
#pragma unroll
        for (int nf = 0; nf < 8; nf++)
#pragma unroll
            for (int q = 0; q < 4; q++) acc[mf][nf][q] = 0.0f;

    const float* p0 = g_po + ((size_t)b * NP + n0) * CI;
    const float* p1 = g_po + ((size_t)(BB + b) * NP + n0) * CI;

    for (int o0 = 0; o0 < CI; o0 += 64) {
        __syncthreads();
#pragma unroll
        for (int i = 0; i < 8; i++) {
            int id = i * 256 + t;
            int row = id >> 4, ch = id & 15;
            float4 a = *(const float4*)&p0[(size_t)row * CI + o0 + ch * 4];
            float4 c = *(const float4*)&p1[(size_t)row * CI + o0 + ch * 4];
            float w0 = wgt0[row], w1 = wgt1[row];
            float m[4] = {a.x * w0 + c.x * w1, a.y * w0 + c.y * w1,
                          a.z * w0 + c.z * w1, a.w * w0 + c.w * w1};
            __half h[4], l[4];
#pragma unroll
            for (int q = 0; q < 4; q++) {
                h[q] = __float2half_rn(m[q]);
                l[q] = __float2half_rn(m[q] - __half2float(h[q]));
            }
            u32 sw = SWZ128(row * 128 + ch * 8);
            *(uint2*)(ps + sw)         = make_uint2(h2u(h[0], h[1]), h2u(h[2], h[3]));
            *(uint2*)(ps + 16384 + sw) = make_uint2(h2u(l[0], l[1]), h2u(l[2], l[3]));
        }
#pragma unroll
        for (int i = 0; i < 4; i++) {
            int id = i * 256 + t;
            int row = id >> 3, ch = id & 7;
            u32 sw = SWZ128(row * 128 + ch * 16);
            cpa(s32 + 32768 + sw, g_wwh + (size_t)(cb + row) * CI + o0 + ch * 8);
            cpa(s32 + 49152 + sw, g_wwl + (size_t)(cb + row) * CI + o0 + ch * 8);
        }
        CP_COMMIT();
        CP_WAIT0();
        __syncthreads();

#pragma unroll
        for (int kc = 0; kc < 4; kc++) {
            u32 Ah[2][4], Al[2][4], B[4][4];
#pragma unroll
            for (int mf = 0; mf < 2; mf++)
                ldm4(Ah[mf][0], Ah[mf][1], Ah[mf][2], Ah[mf][3],
                     s32 + SWZ128((wm * 32 + mf * 16 + lrow) * 128 + kc * 32 + lcol));
#pragma unroll
            for (int bf = 0; bf < 4; bf++)
                ldm4(B[bf][0], B[bf][1], B[bf][2], B[bf][3],
                     s32 + 32768 + SWZ128((wn * 64 + bf * 16 + lrow) * 128 + kc * 32 + lcol));
#pragma unroll
            for (int mf = 0; mf < 2; mf++)
#pragma unroll
                for (int bf = 0; bf < 4; bf++) {
                    mma16816(acc[mf][2 * bf],     Ah[mf][0], Ah[mf][1], Ah[mf][2], Ah[mf][3], B[bf][0], B[bf][2]);
                    mma16816(acc[mf][2 * bf + 1], Ah[mf][0], Ah[mf][1], Ah[mf][2], Ah[mf][3], B[bf][1], B[bf][3]);
                }
#pragma unroll
            for (int mf = 0; mf < 2; mf++)
                ldm4(Al[mf][0], Al[mf][1], Al[mf][2], Al[mf][3],
                     s32 + 16384 + SWZ128((wm * 32 + mf * 16 + lrow) * 128 + kc * 32 + lcol));
#pragma unroll
            for (int mf = 0; mf < 2; mf++)
#pragma unroll
                for (int bf = 0; bf < 4; bf++) {
                    mma16816(acc[mf][2 * bf],     Al[mf][0], Al[mf][1], Al[mf][2], Al[mf][3], B[bf][0], B[bf][2]);
                    mma16816(acc[mf][2 * bf + 1], Al[mf][0], Al[mf][1], Al[mf][2], Al[mf][3], B[bf][1], B[bf][3]);
                }
#pragma unroll
            for (int bf = 0; bf < 4; bf++)
                ldm4(B[bf][0], B[bf][1], B[bf][2], B[bf][3],
                     s32 + 49152 + SWZ128((wn * 64 + bf * 16 + lrow) * 128 + kc * 32 + lcol));
#pragma unroll
            for (int mf = 0; mf < 2; mf++)
#pragma unroll
                for (int bf = 0; bf < 4; bf++) {
                    mma16816(acc[mf][2 * bf],     Ah[mf][0], Ah[mf][1], Ah[mf][2], Ah[mf][3], B[bf][0], B[bf][2]);
                    mma16816(acc[mf][2 * bf + 1], Ah[mf][0], Ah[mf][1], Ah[mf][2], Ah[mf][3], B[bf][1], B[bf][3]);
                }
        }
    }
    __syncthreads();

#pragma unroll
    for (int mf = 0; mf < 2; mf++) {
        int nl = wm * 32 + mf * 16 + g;
#pragma unroll
        for (int nf = 0; nf < 8; nf++) {
            int cl = wn * 64 + nf * 8 + c2;
            *(float*)(ps + (cl * 128 + nl) * 4)           = acc[mf][nf][0];
            *(float*)(ps + ((cl + 1) * 128 + nl) * 4)     = acc[mf][nf][1];
            *(float*)(ps + (cl * 128 + nl + 8) * 4)       = acc[mf][nf][2];
            *(float*)(ps + ((cl + 1) * 128 + nl + 8) * 4) = acc[mf][nf][3];
        }
    }
    __syncthreads();

    int r = t >> 1, part = t & 1;
    float bv = wb[cb + r];
    size_t base = ((size_t)b * CC + cb + r) * NP + n0 + part * 64;
#pragma unroll
    for (int k = 0; k < 16; k++) {
        float4 v  = *(float4*)(ps + (r * 128 + part * 64 + k * 4) * 4);
        float4 xv = *(const float4*)&x[base + k * 4];
        float4 rr = make_float4(v.x + bv + xv.x, v.y + bv + xv.y,
                                v.z + bv + xv.z, v.w + bv + xv.w);
        *(float4*)&out[base + k * 4] = rr;
    }
}

// =================================================================
extern "C" void kernel_launch(void* const* d_in, const int* in_sizes, int n_in,
                              void* d_out, int out_size)
{
    const float* x  = (const float*)d_in[0];
    const float* tw = (const float*)d_in[1];
    const float* tb = (const float*)d_in[2];
    const float* pw = (const float*)d_in[3];
    const float* pb = (const float*)d_in[4];
    const float* gw = (const float*)d_in[5];
    const float* gb = (const float*)d_in[6];
    const float* ww = (const float*)d_in[7];
    const float* wb = (const float*)d_in[8];
    float* out = (float*)d_out;

    cudaFuncSetAttribute(attn_kernel,    cudaFuncAttributeMaxDynamicSharedMemorySize, SMEM_ATTN);
    cudaFuncSetAttribute(proj_kernel,    cudaFuncAttributeMaxDynamicSharedMemorySize, PJX_SMEM);
    cudaFuncSetAttribute(outproj_kernel, cudaFuncAttributeMaxDynamicSharedMemorySize, OP_SMEM);

    conv_all<<<4096 + 128, 256>>>(x, tw, pw, gw, ww);
    proj_kernel<<<dim3(NP / 128, BB), 256, PJX_SMEM>>>(tb, pb, gb);
    attn_kernel<<<dim3(NP / 128, 2, BB), 128, SMEM_ATTN>>>();
    outproj_kernel<<<dim3(NP / 128, CC / 128, BB), 256, OP_SMEM>>>(x, wb, out);
}

// round 13
// speedup vs baseline: 1.0290x; 1.0239x over previous
#include <cuda_runtime.h>
#include <cuda_fp16.h>
#include <math.h>
#include <stdint.h>

#define BB 4
#define CC 256
#define CI 128
#define NP 4096
#define LOG2E 1.4426950408889634f

typedef unsigned long long u64;
typedef unsigned int u32;

// Scratch (device globals: allocation-free rule)
__device__ __half g_twh[CI * CC], g_twl[CI * CC];
__device__ __half g_pwh[CI * CC], g_pwl[CI * CC];
__device__ __half g_gwh[CI * CC], g_gwl[CI * CC];
__device__ __half g_wwh[CC * CI], g_wwl[CC * CI];
__device__ __half g_qh[BB * NP * CI];  // theta(x)*log2e hi         : (b, n, o)
__device__ __half g_qc[BB * NP * CI];  // qh/64 + ql (correction)   : (b, n, o)
__device__ __half g_kh[BB * NP * CI];  // phi(x) hi                 : (b, m, o)
__device__ __half g_kc[BB * NP * CI];  // kh + 64*kl (correction)   : (b, m, o)
__device__ __half g_vt[BB * CI * NP];  // g(x) transposed           : (b, o, m)
__device__ float  g_po[2 * BB * NP * CI];  // unnormalized partial O per kv-split
__device__ float  g_pm[2 * BB * NP];       // partial running max (log2 domain)
__device__ float  g_pl[2 * BB * NP];       // partial running sum

// ---------------- helpers ----------------
__device__ __forceinline__ float ex2(float x) {
    float y;
    asm("ex2.approx.ftz.f32 %0, %1;" : "=f"(y) : "f"(x));
    return y;
}
__device__ __forceinline__ u32 smem_u32(const void* p) {
    u32 a;
    asm("{ .reg .u64 t; cvta.to.shared.u64 t, %1; cvt.u32.u64 %0, t; }" : "=r"(a) : "l"(p));
    return a;
}
__device__ __forceinline__ u32 h2u(__half a, __half b) {
    __half2 h = __halves2half2(a, b);
    return *(u32*)&h;
}

// ---------------- mma.sync / ldmatrix / cp.async ----------------
__device__ __forceinline__ void ldm4(u32& r0, u32& r1, u32& r2, u32& r3, u32 addr) {
    asm volatile("ldmatrix.sync.aligned.m8n8.x4.shared.b16 {%0,%1,%2,%3}, [%4];"
                 : "=r"(r0), "=r"(r1), "=r"(r2), "=r"(r3) : "r"(addr));
}
__device__ __forceinline__ void ldm4t(u32& r0, u32& r1, u32& r2, u32& r3, u32 addr) {
    asm volatile("ldmatrix.sync.aligned.m8n8.x4.trans.shared.b16 {%0,%1,%2,%3}, [%4];"
                 : "=r"(r0), "=r"(r1), "=r"(r2), "=r"(r3) : "r"(addr));
}
__device__ __forceinline__ void mma16816(float* c, u32 a0, u32 a1, u32 a2, u32 a3,
                                         u32 b0, u32 b1) {
    asm volatile(
        "mma.sync.aligned.m16n8k16.row.col.f32.f16.f16.f32 "
        "{%0,%1,%2,%3}, {%4,%5,%6,%7}, {%8,%9}, {%0,%1,%2,%3};"
        : "+f"(c[0]), "+f"(c[1]), "+f"(c[2]), "+f"(c[3])
        : "r"(a0), "r"(a1), "r"(a2), "r"(a3), "r"(b0), "r"(b1));
}
__device__ __forceinline__ void cpa(u32 s, const void* g) {
    asm volatile("cp.async.cg.shared.global [%0], [%1], 16;" :: "r"(s), "l"(g));
}
#define CP_COMMIT() asm volatile("cp.async.commit_group;")
#define CP_WAIT1()  asm volatile("cp.async.wait_group 1;")
#define CP_WAIT0()  asm volatile("cp.async.wait_group 0;")

#define SWZ256(x) ((x) ^ (((x) >> 4) & 0x70))   // 256B rows
#define SWZ128(x) ((x) ^ (((x) >> 3) & 0x70))   // 128B rows

#define HONE 0x3C003C00u   // half2(1.0, 1.0)

// =================================================================
// Kernel 0: fp32 -> fp16 hi/lo conversion for the 4 weight matrices.
// =================================================================
__global__ __launch_bounds__(256) void conv_w(
    const float* __restrict__ tw, const float* __restrict__ pw,
    const float* __restrict__ gw, const float* __restrict__ ww)
{
    int wsel = blockIdx.x >> 5;
    int i = (blockIdx.x & 31) * 1024 + threadIdx.x * 4;
    const float* src = (wsel == 0) ? tw : (wsel == 1) ? pw : (wsel == 2) ? gw : ww;
    __half* dh = (wsel == 0) ? g_twh : (wsel == 1) ? g_pwh : (wsel == 2) ? g_gwh : g_wwh;
    __half* dl = (wsel == 0) ? g_twl : (wsel == 1) ? g_pwl : (wsel == 2) ? g_gwl : g_wwl;

    float4 v = *(const float4*)&src[i];
    __half h0 = __float2half_rn(v.x), h1 = __float2half_rn(v.y);
    __half h2 = __float2half_rn(v.z), h3 = __float2half_rn(v.w);
    __half l0 = __float2half_rn(v.x - __half2float(h0));
    __half l1 = __float2half_rn(v.y - __half2float(h1));
    __half l2 = __float2half_rn(v.z - __half2float(h2));
    __half l3 = __float2half_rn(v.w - __half2float(h3));
    *(uint2*)&dh[i] = make_uint2(h2u(h0, h1), h2u(h2, h3));
    *(uint2*)&dl[i] = make_uint2(h2u(l0, l1), h2u(l2, l3));
}

// =================================================================
// Kernel 1: QKV projections, X-resident mega kernel.
// X slice is read as f32 and converted to hi/lo fp16 INLINE during
// the prologue staging (no global fp16 x round-trip).
// Then z = 0..2 weight loops with double-buffered 32KB W chunks.
// 3-pass hi/lo per chunk: Ah.Bh + Al.Bh + Ah.Bl.
// smem: XH 0..64K | XL 64..128K | Wbuf0 128..160K | Wbuf1 160..192K
// =================================================================
#define PJX_XH   0
#define PJX_XL   65536
#define PJX_W0   131072
#define PJX_W1   163840
#define PJX_SMEM 196608

__device__ __forceinline__ void stage_w(u32 wbase, const __half* Wh,
                                        const __half* Wl, int c0, int t)
{
#pragma unroll
    for (int i = 0; i < 4; i++) {
        int id = i * 256 + t;
        int row = id >> 3, ch = id & 7;
        u32 sw = SWZ128(row * 128 + ch * 16);
        cpa(wbase + sw,         Wh + (size_t)row * CC + c0 + ch * 8);
        cpa(wbase + 16384 + sw, Wl + (size_t)row * CC + c0 + ch * 8);
    }
}

__global__ __launch_bounds__(256, 1) void proj_kernel(
    const float* __restrict__ x,
    const float* __restrict__ tb, const float* __restrict__ pb,
    const float* __restrict__ gb)
{
    extern __shared__ char ps[];
    __shared__ float bias_s[3][128];
    const u32 s32 = smem_u32(ps);
    const int b  = blockIdx.y;
    const int n0 = blockIdx.x * 128;
    const int t  = threadIdx.x;
    const int lane = t & 31;
    const int w  = t >> 5;
    const int wm = w & 3;
    const int wn = w >> 2;

    const int lrow = lane & 15;
    const int lcol = (lane >> 4) * 16;
    const int g    = lane >> 2;
    const int c2   = (lane & 3) * 2;
    const int trow = ((lane >> 4) << 3) + (lane & 7);
    const int tcol = ((lane >> 3) & 1) * 8;

    const __half* WH[3] = {g_twh, g_pwh, g_gwh};
    const __half* WL[3] = {g_twl, g_pwl, g_gwl};
    const float*  Xf = x + (size_t)b * CC * NP + n0;

    if (t < 128) {
        bias_s[0][t] = tb[t];
        bias_s[1][t] = pb[t];
        bias_s[2][t] = gb[t];
    }

    // ---- prologue: W chunks 0,1 via cp.async; X converted inline ----
    stage_w(s32 + PJX_W0, WH[0], WL[0], 0, t);
    CP_COMMIT();
    stage_w(s32 + PJX_W1, WH[0], WL[0], 64, t);
    CP_COMMIT();

    // X: [256c][128n] f32 -> hi/lo halves in swizzled smem
#pragma unroll 4
    for (int i = 0; i < 32; i++) {
        int id  = i * 256 + t;
        int row = id >> 5;            // c row 0..255
        int c4  = (id & 31) * 4;      // n col 0..124
        float4 v = *(const float4*)&Xf[(size_t)row * NP + c4];
        __half h0 = __float2half_rn(v.x), h1 = __float2half_rn(v.y);
        __half h2 = __float2half_rn(v.z), h3 = __float2half_rn(v.w);
        __half l0 = __float2half_rn(v.x - __half2float(h0));
        __half l1 = __float2half_rn(v.y - __half2float(h1));
        __half l2 = __float2half_rn(v.z - __half2float(h2));
        __half l3 = __float2half_rn(v.w - __half2float(h3));
        u32 off = SWZ256(row * 256 + c4 * 2);
        *(uint2*)(ps + PJX_XH + off) = make_uint2(h2u(h0, h1), h2u(h2, h3));
        *(uint2*)(ps + PJX_XL + off) = make_uint2(h2u(l0, l1), h2u(l2, l3));
    }

    float acc[2][8][4];

    for (int q = 0; q < 12; q++) {
        const int z  = q >> 2;
        const int c0 = (q & 3) * 64;
        const u32 wb = s32 + ((q & 1) ? PJX_W1 : PJX_W0);

        if ((q & 3) == 0) {
#pragma unroll
            for (int mf = 0; mf < 2; mf++)
#pragma unroll
                for (int nf = 0; nf < 8; nf++)
#pragma unroll
                    for (int p = 0; p < 4; p++) acc[mf][nf][p] = 0.0f;
        }

        CP_WAIT1();
        __syncthreads();

#pragma unroll
        for (int kc = 0; kc < 4; kc++) {
            u32 Ah[2][4], Al[2][4], B[4][4];
#pragma unroll
            for (int mf = 0; mf < 2; mf++)
                ldm4t(Ah[mf][0], Ah[mf][1], Ah[mf][2], Ah[mf][3],
                      s32 + PJX_XH + SWZ256((c0 + kc * 16 + trow) * 256 + (wm * 32 + mf * 16 + tcol) * 2));
#pragma unroll
            for (int bf = 0; bf < 4; bf++)
                ldm4(B[bf][0], B[bf][1], B[bf][2], B[bf][3],
                     wb + SWZ128((wn * 64 + bf * 16 + lrow) * 128 + kc * 32 + lcol));
#pragma unroll
            for (int mf = 0; mf < 2; mf++)
#pragma unroll
                for (int bf = 0; bf < 4; bf++) {
                    mma16816(acc[mf][2 * bf],     Ah[mf][0], Ah[mf][1], Ah[mf][2], Ah[mf][3], B[bf][0], B[bf][2]);
                    mma16816(acc[mf][2 * bf + 1], Ah[mf][0], Ah[mf][1], Ah[mf][2], Ah[mf][3], B[bf][1], B[bf][3]);
                }
#pragma unroll
            for (int mf = 0; mf < 2; mf++)
                ldm4t(Al[mf][0], Al[mf][1], Al[mf][2], Al[mf][3],
                      s32 + PJX_XL + SWZ256((c0 + kc * 16 + trow) * 256 + (wm * 32 + mf * 16 + tcol) * 2));
#pragma unroll
            for (int mf = 0; mf < 2; mf++)
#pragma unroll
                for (int bf = 0; bf < 4; bf++) {
                    mma16816(acc[mf][2 * bf],     Al[mf][0], Al[mf][1], Al[mf][2], Al[mf][3], B[bf][0], B[bf][2]);
                    mma16816(acc[mf][2 * bf + 1], Al[mf][0], Al[mf][1], Al[mf][2], Al[mf][3], B[bf][1], B[bf][3]);
                }
#pragma unroll
            for (int bf = 0; bf < 4; bf++)
                ldm4(B[bf][0], B[bf][1], B[bf][2], B[bf][3],
                     wb + 16384 + SWZ128((wn * 64 + bf * 16 + lrow) * 128 + kc * 32 + lcol));
#pragma unroll
            for (int mf = 0; mf < 2; mf++)
#pragma unroll
                for (int bf = 0; bf < 4; bf++) {
                    mma16816(acc[mf][2 * bf],     Ah[mf][0], Ah[mf][1], Ah[mf][2], Ah[mf][3], B[bf][0], B[bf][2]);
                    mma16816(acc[mf][2 * bf + 1], Ah[mf][0], Ah[mf][1], Ah[mf][2], Ah[mf][3], B[bf][1], B[bf][3]);
                }
        }

        __syncthreads();
        if (q + 2 < 12) {
            int q2 = q + 2;
            stage_w(s32 + ((q2 & 1) ? PJX_W1 : PJX_W0),
                    WH[q2 >> 2], WL[q2 >> 2], (q2 & 3) * 64, t);
        }
        CP_COMMIT();

        if ((q & 3) == 3) {
            if (z == 2) {
#pragma unroll
                for (int mf = 0; mf < 2; mf++) {
                    int nl = wm * 32 + mf * 16 + g;
#pragma unroll
                    for (int nf = 0; nf < 8; nf++) {
                        int o = wn * 64 + nf * 8 + c2;
                        __half h00 = __float2half_rn(acc[mf][nf][0] + bias_s[2][o]);
                        __half h01 = __float2half_rn(acc[mf][nf][1] + bias_s[2][o + 1]);
                        __half h10 = __float2half_rn(acc[mf][nf][2] + bias_s[2][o]);
                        __half h11 = __float2half_rn(acc[mf][nf][3] + bias_s[2][o + 1]);
                        *(__half*)(ps + (o * 128 + nl) * 2)           = h00;
                        *(__half*)(ps + ((o + 1) * 128 + nl) * 2)     = h01;
                        *(__half*)(ps + (o * 128 + nl + 8) * 2)       = h10;
                        *(__half*)(ps + ((o + 1) * 128 + nl + 8) * 2) = h11;
                    }
                }
                __syncthreads();
                int o = t >> 1, part = t & 1;
                __half* dst = g_vt + ((size_t)b * CI + o) * NP + n0 + part * 64;
#pragma unroll
                for (int k = 0; k < 8; k++)
                    *(uint4*)&dst[k * 8] = *(uint4*)(ps + (o * 128 + part * 64 + k * 8) * 2);
            } else {
                __half* dh = (z == 0) ? g_qh : g_kh;
                __half* dc = (z == 0) ? g_qc : g_kc;
                const float sc = (z == 0) ? LOG2E : 1.0f;
                const size_t bq = (size_t)b * NP + n0;
#pragma unroll
                for (int mf = 0; mf < 2; mf++) {
                    int nl = wm * 32 + mf * 16 + g;
#pragma unroll
                    for (int nf = 0; nf < 8; nf++) {
                        int o = wn * 64 + nf * 8 + c2;
                        float bv0 = bias_s[z][o], bv1 = bias_s[z][o + 1];
                        float v[4];
                        v[0] = (acc[mf][nf][0] + bv0) * sc;
                        v[1] = (acc[mf][nf][1] + bv1) * sc;
                        v[2] = (acc[mf][nf][2] + bv0) * sc;
                        v[3] = (acc[mf][nf][3] + bv1) * sc;
                        __half hh[4], cc[4];
#pragma unroll
                        for (int p = 0; p < 4; p++) {
                            __half h = __float2half_rn(v[p]);
                            float  hf = __half2float(h);
                            float  l  = v[p] - hf;
                            hh[p] = h;
                            cc[p] = (z == 0) ? __float2half_rn(hf * 0.015625f + l)
                                             : __float2half_rn(hf + 64.0f * l);
                        }
                        size_t i0 = (bq + nl) * CI + o;
                        size_t i1 = i0 + (size_t)8 * CI;
                        *(u32*)&dh[i0] = h2u(hh[0], hh[1]);
                        *(u32*)&dc[i0] = h2u(cc[0], cc[1]);
                        *(u32*)&dh[i1] = h2u(hh[2], hh[3]);
                        *(u32*)&dc[i1] = h2u(cc[2], cc[3]);
                    }
                }
            }
        }
    }
}

// =================================================================
// Kernel 2: flash attention, 128 threads/CTA (4 warps x 32 q-rows),
// 2-pass QK^T, KV-split 2, swizzled smem, 2 CTAs/SM.
// f32 ex2; l via ones-MMA.  (R10 version — known best)
// =================================================================
#define OFF_QH 0
#define OFF_QC 32768
#define OFF_KH 65536
#define OFF_KC 81920
#define OFF_V  98304
#define SMEM_ATTN 114688
#define KV_TILES 32

__device__ __forceinline__ void load_k(u32 s32, int m0,
                                       const __half* gkh, const __half* gkc, int t)
{
#pragma unroll
    for (int i = 0; i < 8; i++) {
        int id = i * 128 + t;
        int row = id >> 4, c = id & 15;
        u32 sw = SWZ256(row * 256 + c * 16);
        cpa(s32 + OFF_KH + sw, gkh + (size_t)(m0 + row) * CI + c * 8);
        cpa(s32 + OFF_KC + sw, gkc + (size_t)(m0 + row) * CI + c * 8);
    }
}
__device__ __forceinline__ void load_v(u32 s32, int m0, const __half* gvt, int t)
{
#pragma unroll
    for (int i = 0; i < 8; i++) {
        int id = i * 128 + t;
        int row = id >> 3, c = id & 7;
        cpa(s32 + OFF_V + SWZ128(row * 128 + c * 16), gvt + (size_t)row * NP + m0 + c * 8);
    }
}

__global__ __launch_bounds__(128, 2) void attn_kernel()
{
    extern __shared__ __align__(128) char smem[];
    const u32 s32   = smem_u32(smem);
    const int t     = threadIdx.x;
    const int lane  = t & 31;
    const int wr    = (t >> 5) * 32;
    const int row0  = blockIdx.x * 128;
    const int split = blockIdx.y;
    const int b     = blockIdx.z;
    const int kv0   = split * (NP / 2);

    const int lrow = lane & 15;
    const int lcol = (lane >> 4) * 16;
    const int g    = lane >> 2;
    const int c2   = (lane & 3) * 2;

    const __half* gqh = g_qh + ((size_t)b * NP + row0) * CI;
    const __half* gqc = g_qc + ((size_t)b * NP + row0) * CI;
    const __half* gkh = g_kh + ((size_t)b * NP + kv0) * CI;
    const __half* gkc = g_kc + ((size_t)b * NP + kv0) * CI;
    const __half* gvt = g_vt + (size_t)b * CI * NP + kv0;

#pragma unroll
    for (int i = 0; i < 16; i++) {
        int id = i * 128 + t;
        int row = id >> 4, c = id & 15;
        u32 sw = SWZ256(row * 256 + c * 16);
        cpa(s32 + OFF_QH + sw, gqh + (size_t)row * CI + c * 8);
        cpa(s32 + OFF_QC + sw, gqc + (size_t)row * CI + c * 8);
    }
    load_k(s32, 0, gkh, gkc, t);
    CP_COMMIT();
    load_v(s32, 0, gvt, t);
    CP_COMMIT();

    float o[2][16][4];
#pragma unroll
    for (int mf = 0; mf < 2; mf++)
#pragma unroll
        for (int nf = 0; nf < 16; nf++)
#pragma unroll
            for (int q = 0; q < 4; q++) o[mf][nf][q] = 0.0f;
    float mrun[2][2] = {{-1e30f, -1e30f}, {-1e30f, -1e30f}};
    float lrun[2][2] = {{0.0f, 0.0f}, {0.0f, 0.0f}};

    for (int tile = 0; tile < KV_TILES; tile++) {
        CP_WAIT1();
        __syncthreads();

        float s[2][8][4];
#pragma unroll
        for (int mf = 0; mf < 2; mf++)
#pragma unroll
            for (int nf = 0; nf < 8; nf++)
#pragma unroll
                for (int q = 0; q < 4; q++) s[mf][nf][q] = 0.0f;

#pragma unroll
        for (int kc = 0; kc < 8; kc++) {
            u32 qa[2][4];
#pragma unroll
            for (int mf = 0; mf < 2; mf++)
                ldm4(qa[mf][0], qa[mf][1], qa[mf][2], qa[mf][3],
                     s32 + OFF_QH + SWZ256((wr + mf * 16 + lrow) * 256 + kc * 32 + lcol));
#pragma unroll
            for (int nb = 0; nb < 4; nb++) {
                u32 k0, k1, k2, k3;
                ldm4(k0, k1, k2, k3,
                     s32 + OFF_KH + SWZ256((nb * 16 + lrow) * 256 + kc * 32 + lcol));
#pragma unroll
                for (int mf = 0; mf < 2; mf++) {
                    mma16816(s[mf][2 * nb],     qa[mf][0], qa[mf][1], qa[mf][2], qa[mf][3], k0, k2);
                    mma16816(s[mf][2 * nb + 1], qa[mf][0], qa[mf][1], qa[mf][2], qa[mf][3], k1, k3);
                }
            }
        }
#pragma unroll
        for (int mf = 0; mf < 2; mf++)
#pragma unroll
            for (int nf = 0; nf < 8; nf++)
#pragma unroll
                for (int q = 0; q < 4; q++) s[mf][nf][q] *= 0.984375f;

#pragma unroll
        for (int kc = 0; kc < 8; kc++) {
            u32 qa[2][4];
#pragma unroll
            for (int mf = 0; mf < 2; mf++)
                ldm4(qa[mf][0], qa[mf][1], qa[mf][2], qa[mf][3],
                     s32 + OFF_QC + SWZ256((wr + mf * 16 + lrow) * 256 + kc * 32 + lcol));
#pragma unroll
            for (int nb = 0; nb < 4; nb++) {
                u32 k0, k1, k2, k3;
                ldm4(k0, k1, k2, k3,
                     s32 + OFF_KC + SWZ256((nb * 16 + lrow) * 256 + kc * 32 + lcol));
#pragma unroll
                for (int mf = 0; mf < 2; mf++) {
                    mma16816(s[mf][2 * nb],     qa[mf][0], qa[mf][1], qa[mf][2], qa[mf][3], k0, k2);
                    mma16816(s[mf][2 * nb + 1], qa[mf][0], qa[mf][1], qa[mf][2], qa[mf][3], k1, k3);
                }
            }
        }

        __syncthreads();
        if (tile + 1 < KV_TILES) load_k(s32, (tile + 1) * 64, gkh, gkc, t);
        CP_COMMIT();

        // ---- online softmax (f32 ex2; l via ones-MMA) ----
        float corr[2][2];
        u32   p[2][4][4];
#pragma unroll
        for (int mf = 0; mf < 2; mf++) {
            float mx0 = fmaxf(s[mf][0][0], s[mf][0][1]);
            float mx1 = fmaxf(s[mf][0][2], s[mf][0][3]);
#pragma unroll
            for (int nf = 1; nf < 8; nf++) {
                mx0 = fmaxf(mx0, fmaxf(s[mf][nf][0], s[mf][nf][1]));
                mx1 = fmaxf(mx1, fmaxf(s[mf][nf][2], s[mf][nf][3]));
            }
            mx0 = fmaxf(mx0, __shfl_xor_sync(0xffffffffu, mx0, 1));
            mx0 = fmaxf(mx0, __shfl_xor_sync(0xffffffffu, mx0, 2));
            mx1 = fmaxf(mx1, __shfl_xor_sync(0xffffffffu, mx1, 1));
            mx1 = fmaxf(mx1, __shfl_xor_sync(0xffffffffu, mx1, 2));
            float mnew0 = fmaxf(mrun[mf][0], mx0);
            float mnew1 = fmaxf(mrun[mf][1], mx1);
            corr[mf][0] = ex2(mrun[mf][0] - mnew0);
            corr[mf][1] = ex2(mrun[mf][1] - mnew1);
            mrun[mf][0] = mnew0;
            mrun[mf][1] = mnew1;

#pragma unroll
            for (int kc2 = 0; kc2 < 4; kc2++) {
#pragma unroll
                for (int half = 0; half < 2; half++) {
                    int nf = 2 * kc2 + half;
                    float e0 = ex2(s[mf][nf][0] - mnew0);
                    float e1 = ex2(s[mf][nf][1] - mnew0);
                    float e2 = ex2(s[mf][nf][2] - mnew1);
                    float e3 = ex2(s[mf][nf][3] - mnew1);
                    p[mf][kc2][2 * half]     = h2u(__float2half_rn(e0), __float2half_rn(e1));
                    p[mf][kc2][2 * half + 1] = h2u(__float2half_rn(e2), __float2half_rn(e3));
                }
            }
        }

        // l_tile = P . 1  (8 HMMA, no LDS, no shuffles)
        float lc[2][4] = {{0.0f, 0.0f, 0.0f, 0.0f}, {0.0f, 0.0f, 0.0f, 0.0f}};
#pragma unroll
        for (int mf = 0; mf < 2; mf++)
#pragma unroll
            for (int kc2 = 0; kc2 < 4; kc2++)
                mma16816(lc[mf], p[mf][kc2][0], p[mf][kc2][1],
                         p[mf][kc2][2], p[mf][kc2][3], HONE, HONE);
#pragma unroll
        for (int mf = 0; mf < 2; mf++) {
            lrun[mf][0] = lrun[mf][0] * corr[mf][0] + lc[mf][0];
            lrun[mf][1] = lrun[mf][1] * corr[mf][1] + lc[mf][2];
        }

        if (__any_sync(0xffffffffu,
                       fminf(fminf(corr[0][0], corr[0][1]),
                             fminf(corr[1][0], corr[1][1])) < 0.99999f)) {
#pragma unroll
            for (int mf = 0; mf < 2; mf++)
#pragma unroll
                for (int nf = 0; nf < 16; nf++) {
                    o[mf][nf][0] *= corr[mf][0]; o[mf][nf][1] *= corr[mf][0];
                    o[mf][nf][2] *= corr[mf][1]; o[mf][nf][3] *= corr[mf][1];
                }
        }

        CP_WAIT1();
        __syncthreads();

#pragma unroll
        for (int kc2 = 0; kc2 < 4; kc2++) {
#pragma unroll
            for (int dg = 0; dg < 8; dg++) {
                u32 v0, v1, v2, v3;
                ldm4(v0, v1, v2, v3,
                     s32 + OFF_V + SWZ128((dg * 16 + lrow) * 128 + kc2 * 32 + lcol));
#pragma unroll
                for (int mf = 0; mf < 2; mf++) {
                    mma16816(o[mf][2 * dg],
                             p[mf][kc2][0], p[mf][kc2][1], p[mf][kc2][2], p[mf][kc2][3], v0, v2);
                    mma16816(o[mf][2 * dg + 1],
                             p[mf][kc2][0], p[mf][kc2][1], p[mf][kc2][2], p[mf][kc2][3], v1, v3);
                }
            }
        }

        __syncthreads();
        if (tile + 1 < KV_TILES) load_v(s32, (tile + 1) * 64, gvt, t);
        CP_COMMIT();
    }

    float* po = g_po + ((size_t)(split * BB + b) * NP + row0 + wr) * CI;
    float* pm = g_pm + (size_t)(split * BB + b) * NP + row0 + wr;
    float* pl = g_pl + (size_t)(split * BB + b) * NP + row0 + wr;
#pragma unroll
    for (int mf = 0; mf < 2; mf++) {
        int r0 = mf * 16 + g;
#pragma unroll
        for (int nf = 0; nf < 16; nf++) {
            *(float2*)&po[(size_t)r0 * CI + nf * 8 + c2] =
                make_float2(o[mf][nf][0], o[mf][nf][1]);
            *(float2*)&po[(size_t)(r0 + 8) * CI + nf * 8 + c2] =
                make_float2(o[mf][nf][2], o[mf][nf][3]);
        }
        if ((lane & 3) == 0) {
            pm[r0] = mrun[mf][0]; pm[r0 + 8] = mrun[mf][1];
            pl[r0] = lrun[mf][0]; pl[r0 + 8] = lrun[mf][1];
        }
    }
}

// =================================================================
// Kernel 3: fused merge + output projection (exact R8 version).
// =================================================================
#define OP_SMEM 65536

__global__ __launch_bounds__(256, 2) void outproj_kernel(
    const float* __restrict__ x, const float* __restrict__ wb,
    float* __restrict__ out)
{
    extern __shared__ char ps[];
    __shared__ float wgt0[128], wgt1[128];
    const u32 s32 = smem_u32(ps);
    const int b  = blockIdx.z;
    const int cb = blockIdx.y * 128;
    const int n0 = blockIdx.x * 128;
    const int t  = threadIdx.x;
    const int lane = t & 31;
    const int w  = t >> 5;
    const int wm = w & 3;
    const int wn = w >> 2;
    const int lrow = lane & 15;
    const int lcol = (lane >> 4) * 16;
    const int g    = lane >> 2;
    const int c2   = (lane & 3) * 2;

    if (t < 128) {
        int bn = b * NP + n0 + t;
        float m0 = g_pm[bn], m1 = g_pm[BB * NP + bn];
        float l0 = g_pl[bn], l1 = g_pl[BB * NP + bn];
        float m  = fmaxf(m0, m1);
        float w0 = ex2(m0 - m), w1 = ex2(m1 - m);
        float inv = 1.0f / (w0 * l0 + w1 * l1);
        wgt0[t] = w0 * inv;
        wgt1[t] = w1 * inv;
    }
    __syncthreads();

    float acc[2][8][4];
#pragma unroll
    for (int mf = 0; mf < 2; mf++)
#pragma unroll
        for (int nf = 0; nf < 8; nf++)
#pragma unroll
            for (int q = 0; q < 4; q++) acc[mf][nf][q] = 0.0f;

    const float* p0 = g_po + ((size_t)b * NP + n0) * CI;
    const float* p1 = g_po + ((size_t)(BB + b) * NP + n0) * CI;

    for (int o0 = 0; o0 < CI; o0 += 64) {
        __syncthreads();
#pragma unroll
        for (int i = 0; i < 8; i++) {
            int id = i * 256 + t;
            int row = id >> 4, ch = id & 15;
            float4 a = *(const float4*)&p0[(size_t)row * CI + o0 + ch * 4];
            float4 c = *(const float4*)&p1[(size_t)row * CI + o0 + ch * 4];
            float w0 = wgt0[row], w1 = wgt1[row];
            float m[4] = {a.x * w0 + c.x * w1, a.y * w0 + c.y * w1,
                          a.z * w0 + c.z * w1, a.w * w0 + c.w * w1};
            __half h[4], l[4];
#pragma unroll
            for (int q = 0; q < 4; q++) {
                h[q] = __float2half_rn(m[q]);
                l[q] = __float2half_rn(m[q] - __half2float(h[q]));
            }
            u32 sw = SWZ128(row * 128 + ch * 8);
            *(uint2*)(ps + sw)         = make_uint2(h2u(h[0], h[1]), h2u(h[2], h[3]));
            *(uint2*)(ps + 16384 + sw) = make_uint2(h2u(l[0], l[1]), h2u(l[2], l[3]));
        }
#pragma unroll
        for (int i = 0; i < 4; i++) {
            int id = i * 256 + t;
            int row = id >> 3, ch = id & 7;
            u32 sw = SWZ128(row * 128 + ch * 16);
            cpa(s32 + 32768 + sw, g_wwh + (size_t)(cb + row) * CI + o0 + ch * 8);
            cpa(s32 + 49152 + sw, g_wwl + (size_t)(cb + row) * CI + o0 + ch * 8);
        }
        CP_COMMIT();
        CP_WAIT0();
        __syncthreads();

#pragma unroll
        for (int kc = 0; kc < 4; kc++) {
            u32 Ah[2][4], Al[2][4], B[4][4];
#pragma unroll
            for (int mf = 0; mf < 2; mf++)
                ldm4(Ah[mf][0], Ah[mf][1], Ah[mf][2], Ah[mf][3],
                     s32 + SWZ128((wm * 32 + mf * 16 + lrow) * 128 + kc * 32 + lcol));
#pragma unroll
            for (int bf = 0; bf < 4; bf++)
                ldm4(B[bf][0], B[bf][1], B[bf][2], B[bf][3],
                     s32 + 32768 + SWZ128((wn * 64 + bf * 16 + lrow) * 128 + kc * 32 + lcol));
#pragma unroll
            for (int mf = 0; mf < 2; mf++)
#pragma unroll
                for (int bf = 0; bf < 4; bf++) {
                    mma16816(acc[mf][2 * bf],     Ah[mf][0], Ah[mf][1], Ah[mf][2], Ah[mf][3], B[bf][0], B[bf][2]);
                    mma16816(acc[mf][2 * bf + 1], Ah[mf][0], Ah[mf][1], Ah[mf][2], Ah[mf][3], B[bf][1], B[bf][3]);
                }
#pragma unroll
            for (int mf = 0; mf < 2; mf++)
                ldm4(Al[mf][0], Al[mf][1], Al[mf][2], Al[mf][3],
                     s32 + 16384 + SWZ128((wm * 32 + mf * 16 + lrow) * 128 + kc * 32 + lcol));
#pragma unroll
            for (int mf = 0; mf < 2; mf++)
#pragma unroll
                for (int bf = 0; bf < 4; bf++) {
                    mma16816(acc[mf][2 * bf],     Al[mf][0], Al[mf][1], Al[mf][2], Al[mf][3], B[bf][0], B[bf][2]);
                    mma16816(acc[mf][2 * bf + 1], Al[mf][0], Al[mf][1], Al[mf][2], Al[mf][3], B[bf][1], B[bf][3]);
                }
#pragma unroll
            for (int bf = 0; bf < 4; bf++)
                ldm4(B[bf][0], B[bf][1], B[bf][2], B[bf][3],
                     s32 + 49152 + SWZ128((wn * 64 + bf * 16 + lrow) * 128 + kc * 32 + lcol));
#pragma unroll
            for (int mf = 0; mf < 2; mf++)
#pragma unroll
                for (int bf = 0; bf < 4; bf++) {
                    mma16816(acc[mf][2 * bf],     Ah[mf][0], Ah[mf][1], Ah[mf][2], Ah[mf][3], B[bf][0], B[bf][2]);
                    mma16816(acc[mf][2 * bf + 1], Ah[mf][0], Ah[mf][1], Ah[mf][2], Ah[mf][3], B[bf][1], B[bf][3]);
                }
        }
    }
    __syncthreads();

#pragma unroll
    for (int mf = 0; mf < 2; mf++) {
        int nl = wm * 32 + mf * 16 + g;
#pragma unroll
        for (int nf = 0; nf < 8; nf++) {
            int cl = wn * 64 + nf * 8 + c2;
            *(float*)(ps + (cl * 128 + nl) * 4)           = acc[mf][nf][0];
            *(float*)(ps + ((cl + 1) * 128 + nl) * 4)     = acc[mf][nf][1];
            *(float*)(ps + (cl * 128 + nl + 8) * 4)       = acc[mf][nf][2];
            *(float*)(ps + ((cl + 1) * 128 + nl + 8) * 4) = acc[mf][nf][3];
        }
    }
    __syncthreads();

    int r = t >> 1, part = t & 1;
    float bv = wb[cb + r];
    size_t base = ((size_t)b * CC + cb + r) * NP + n0 + part * 64;
#pragma unroll
    for (int k = 0; k < 16; k++) {
        float4 v  = *(float4*)(ps + (r * 128 + part * 64 + k * 4) * 4);
        float4 xv = *(const float4*)&x[base + k * 4];
        float4 rr = make_float4(v.x + bv + xv.x, v.y + bv + xv.y,
                                v.z + bv + xv.z, v.w + bv + xv.w);
        *(float4*)&out[base + k * 4] = rr;
    }
}

// =================================================================
extern "C" void kernel_launch(void* const* d_in, const int* in_sizes, int n_in,
                              void* d_out, int out_size)
{
    const float* x  = (const float*)d_in[0];
    const float* tw = (const float*)d_in[1];
    const float* tb = (const float*)d_in[2];
    const float* pw = (const float*)d_in[3];
    const float* pb = (const float*)d_in[4];
    const float* gw = (const float*)d_in[5];
    const float* gb = (const float*)d_in[6];
    const float* ww = (const float*)d_in[7];
    const float* wb = (const float*)d_in[8];
    float* out = (float*)d_out;

    cudaFuncSetAttribute(attn_kernel,    cudaFuncAttributeMaxDynamicSharedMemorySize, SMEM_ATTN);
    cudaFuncSetAttribute(proj_kernel,    cudaFuncAttributeMaxDynamicSharedMemorySize, PJX_SMEM);
    cudaFuncSetAttribute(outproj_kernel, cudaFuncAttributeMaxDynamicSharedMemorySize, OP_SMEM);

    conv_w<<<128, 256>>>(tw, pw, gw, ww);
    proj_kernel<<<dim3(NP / 128, BB), 256, PJX_SMEM>>>(x, tb, pb, gb);
    attn_kernel<<<dim3(NP / 128, 2, BB), 128, SMEM_ATTN>>>();
    outproj_kernel<<<dim3(NP / 128, CC / 128, BB), 256, OP_SMEM>>>(x, wb, out);
}

// round 14
// speedup vs baseline: 1.0336x; 1.0044x over previous
#include <cuda_runtime.h>
#include <cuda_fp16.h>
#include <math.h>
#include <stdint.h>

#define BB 4
#define CC 256
#define CI 128
#define NP 4096
#define LOG2E 1.4426950408889634f

typedef unsigned long long u64;
typedef unsigned int u32;

// Scratch (device globals: allocation-free rule)
__device__ __half g_twh[CI * CC], g_twl[CI * CC];
__device__ __half g_pwh[CI * CC], g_pwl[CI * CC];
__device__ __half g_gwh[CI * CC], g_gwl[CI * CC];
__device__ __half g_wwh[CC * CI], g_wwl[CC * CI];
__device__ __half g_qh[BB * NP * CI];  // theta(x)*log2e hi         : (b, n, o)
__device__ __half g_qc[BB * NP * CI];  // qh/64 + ql (correction)   : (b, n, o)
__device__ __half g_kh[BB * NP * CI];  // phi(x) hi                 : (b, m, o)
__device__ __half g_kc[BB * NP * CI];  // kh + 64*kl (correction)   : (b, m, o)
__device__ __half g_vt[BB * CI * NP];  // g(x) transposed           : (b, o, m)
__device__ float  g_po[2 * BB * NP * CI];  // unnormalized partial O per kv-split
__device__ float  g_pm[2 * BB * NP];       // partial running max (log2 domain)
__device__ float  g_pl[2 * BB * NP];       // partial running sum

// ---------------- helpers ----------------
__device__ __forceinline__ float ex2(float x) {
    float y;
    asm("ex2.approx.ftz.f32 %0, %1;" : "=f"(y) : "f"(x));
    return y;
}
__device__ __forceinline__ u32 smem_u32(const void* p) {
    u32 a;
    asm("{ .reg .u64 t; cvta.to.shared.u64 t, %1; cvt.u32.u64 %0, t; }" : "=r"(a) : "l"(p));
    return a;
}
__device__ __forceinline__ u32 h2u(__half a, __half b) {
    __half2 h = __halves2half2(a, b);
    return *(u32*)&h;
}

// ---------------- mma.sync / ldmatrix / cp.async ----------------
__device__ __forceinline__ void ldm4(u32& r0, u32& r1, u32& r2, u32& r3, u32 addr) {
    asm volatile("ldmatrix.sync.aligned.m8n8.x4.shared.b16 {%0,%1,%2,%3}, [%4];"
                 : "=r"(r0), "=r"(r1), "=r"(r2), "=r"(r3) : "r"(addr));
}
__device__ __forceinline__ void ldm4t(u32& r0, u32& r1, u32& r2, u32& r3, u32 addr) {
    asm volatile("ldmatrix.sync.aligned.m8n8.x4.trans.shared.b16 {%0,%1,%2,%3}, [%4];"
                 : "=r"(r0), "=r"(r1), "=r"(r2), "=r"(r3) : "r"(addr));
}
__device__ __forceinline__ void mma16816(float* c, u32 a0, u32 a1, u32 a2, u32 a3,
                                         u32 b0, u32 b1) {
    asm volatile(
        "mma.sync.aligned.m16n8k16.row.col.f32.f16.f16.f32 "
        "{%0,%1,%2,%3}, {%4,%5,%6,%7}, {%8,%9}, {%0,%1,%2,%3};"
        : "+f"(c[0]), "+f"(c[1]), "+f"(c[2]), "+f"(c[3])
        : "r"(a0), "r"(a1), "r"(a2), "r"(a3), "r"(b0), "r"(b1));
}
__device__ __forceinline__ void cpa(u32 s, const void* g) {
    asm volatile("cp.async.cg.shared.global [%0], [%1], 16;" :: "r"(s), "l"(g));
}
#define CP_COMMIT() asm volatile("cp.async.commit_group;")
#define CP_WAIT1()  asm volatile("cp.async.wait_group 1;")
#define CP_WAIT0()  asm volatile("cp.async.wait_group 0;")

#define SWZ256(x) ((x) ^ (((x) >> 4) & 0x70))   // 256B rows
#define SWZ128(x) ((x) ^ (((x) >> 3) & 0x70))   // 128B rows

#define HONE 0x3C003C00u   // half2(1.0, 1.0)

// =================================================================
// Kernel 0: fp32 -> fp16 hi/lo conversion for the 4 weight matrices.
// =================================================================
__global__ __launch_bounds__(256) void conv_w(
    const float* __restrict__ tw, const float* __restrict__ pw,
    const float* __restrict__ gw, const float* __restrict__ ww)
{
    int wsel = blockIdx.x >> 5;
    int i = (blockIdx.x & 31) * 1024 + threadIdx.x * 4;
    const float* src = (wsel == 0) ? tw : (wsel == 1) ? pw : (wsel == 2) ? gw : ww;
    __half* dh = (wsel == 0) ? g_twh : (wsel == 1) ? g_pwh : (wsel == 2) ? g_gwh : g_wwh;
    __half* dl = (wsel == 0) ? g_twl : (wsel == 1) ? g_pwl : (wsel == 2) ? g_gwl : g_wwl;

    float4 v = *(const float4*)&src[i];
    __half h0 = __float2half_rn(v.x), h1 = __float2half_rn(v.y);
    __half h2 = __float2half_rn(v.z), h3 = __float2half_rn(v.w);
    __half l0 = __float2half_rn(v.x - __half2float(h0));
    __half l1 = __float2half_rn(v.y - __half2float(h1));
    __half l2 = __float2half_rn(v.z - __half2float(h2));
    __half l3 = __float2half_rn(v.w - __half2float(h3));
    *(uint2*)&dh[i] = make_uint2(h2u(h0, h1), h2u(h2, h3));
    *(uint2*)&dl[i] = make_uint2(h2u(l0, l1), h2u(l2, l3));
}

// =================================================================
// Kernel 1: QKV projections, X-resident mega kernel (R13, unchanged).
// =================================================================
#define PJX_XH   0
#define PJX_XL   65536
#define PJX_W0   131072
#define PJX_W1   163840
#define PJX_SMEM 196608

__device__ __forceinline__ void stage_w(u32 wbase, const __half* Wh,
                                        const __half* Wl, int c0, int t)
{
#pragma unroll
    for (int i = 0; i < 4; i++) {
        int id = i * 256 + t;
        int row = id >> 3, ch = id & 7;
        u32 sw = SWZ128(row * 128 + ch * 16);
        cpa(wbase + sw,         Wh + (size_t)row * CC + c0 + ch * 8);
        cpa(wbase + 16384 + sw, Wl + (size_t)row * CC + c0 + ch * 8);
    }
}

__global__ __launch_bounds__(256, 1) void proj_kernel(
    const float* __restrict__ x,
    const float* __restrict__ tb, const float* __restrict__ pb,
    const float* __restrict__ gb)
{
    extern __shared__ char ps[];
    __shared__ float bias_s[3][128];
    const u32 s32 = smem_u32(ps);
    const int b  = blockIdx.y;
    const int n0 = blockIdx.x * 128;
    const int t  = threadIdx.x;
    const int lane = t & 31;
    const int w  = t >> 5;
    const int wm = w & 3;
    const int wn = w >> 2;

    const int lrow = lane & 15;
    const int lcol = (lane >> 4) * 16;
    const int g    = lane >> 2;
    const int c2   = (lane & 3) * 2;
    const int trow = ((lane >> 4) << 3) + (lane & 7);
    const int tcol = ((lane >> 3) & 1) * 8;

    const __half* WH[3] = {g_twh, g_pwh, g_gwh};
    const __half* WL[3] = {g_twl, g_pwl, g_gwl};
    const float*  Xf = x + (size_t)b * CC * NP + n0;

    if (t < 128) {
        bias_s[0][t] = tb[t];
        bias_s[1][t] = pb[t];
        bias_s[2][t] = gb[t];
    }

    // ---- prologue: W chunks 0,1 via cp.async; X converted inline ----
    stage_w(s32 + PJX_W0, WH[0], WL[0], 0, t);
    CP_COMMIT();
    stage_w(s32 + PJX_W1, WH[0], WL[0], 64, t);
    CP_COMMIT();

    // X: [256c][128n] f32 -> hi/lo halves in swizzled smem
#pragma unroll 4
    for (int i = 0; i < 32; i++) {
        int id  = i * 256 + t;
        int row = id >> 5;
        int c4  = (id & 31) * 4;
        float4 v = *(const float4*)&Xf[(size_t)row * NP + c4];
        __half h0 = __float2half_rn(v.x), h1 = __float2half_rn(v.y);
        __half h2 = __float2half_rn(v.z), h3 = __float2half_rn(v.w);
        __half l0 = __float2half_rn(v.x - __half2float(h0));
        __half l1 = __float2half_rn(v.y - __half2float(h1));
        __half l2 = __float2half_rn(v.z - __half2float(h2));
        __half l3 = __float2half_rn(v.w - __half2float(h3));
        u32 off = SWZ256(row * 256 + c4 * 2);
        *(uint2*)(ps + PJX_XH + off) = make_uint2(h2u(h0, h1), h2u(h2, h3));
        *(uint2*)(ps + PJX_XL + off) = make_uint2(h2u(l0, l1), h2u(l2, l3));
    }

    float acc[2][8][4];

    for (int q = 0; q < 12; q++) {
        const int z  = q >> 2;
        const int c0 = (q & 3) * 64;
        const u32 wb = s32 + ((q & 1) ? PJX_W1 : PJX_W0);

        if ((q & 3) == 0) {
#pragma unroll
            for (int mf = 0; mf < 2; mf++)
#pragma unroll
                for (int nf = 0; nf < 8; nf++)
#pragma unroll
                    for (int p = 0; p < 4; p++) acc[mf][nf][p] = 0.0f;
        }

        CP_WAIT1();
        __syncthreads();

#pragma unroll
        for (int kc = 0; kc < 4; kc++) {
            u32 Ah[2][4], Al[2][4], B[4][4];
#pragma unroll
            for (int mf = 0; mf < 2; mf++)
                ldm4t(Ah[mf][0], Ah[mf][1], Ah[mf][2], Ah[mf][3],
                      s32 + PJX_XH + SWZ256((c0 + kc * 16 + trow) * 256 + (wm * 32 + mf * 16 + tcol) * 2));
#pragma unroll
            for (int bf = 0; bf < 4; bf++)
                ldm4(B[bf][0], B[bf][1], B[bf][2], B[bf][3],
                     wb + SWZ128((wn * 64 + bf * 16 + lrow) * 128 + kc * 32 + lcol));
#pragma unroll
            for (int mf = 0; mf < 2; mf++)
#pragma unroll
                for (int bf = 0; bf < 4; bf++) {
                    mma16816(acc[mf][2 * bf],     Ah[mf][0], Ah[mf][1], Ah[mf][2], Ah[mf][3], B[bf][0], B[bf][2]);
                    mma16816(acc[mf][2 * bf + 1], Ah[mf][0], Ah[mf][1], Ah[mf][2], Ah[mf][3], B[bf][1], B[bf][3]);
                }
#pragma unroll
            for (int mf = 0; mf < 2; mf++)
                ldm4t(Al[mf][0], Al[mf][1], Al[mf][2], Al[mf][3],
                      s32 + PJX_XL + SWZ256((c0 + kc * 16 + trow) * 256 + (wm * 32 + mf * 16 + tcol) * 2));
#pragma unroll
            for (int mf = 0; mf < 2; mf++)
#pragma unroll
                for (int bf = 0; bf < 4; bf++) {
                    mma16816(acc[mf][2 * bf],     Al[mf][0], Al[mf][1], Al[mf][2], Al[mf][3], B[bf][0], B[bf][2]);
                    mma16816(acc[mf][2 * bf + 1], Al[mf][0], Al[mf][1], Al[mf][2], Al[mf][3], B[bf][1], B[bf][3]);
                }
#pragma unroll
            for (int bf = 0; bf < 4; bf++)
                ldm4(B[bf][0], B[bf][1], B[bf][2], B[bf][3],
                     wb + 16384 + SWZ128((wn * 64 + bf * 16 + lrow) * 128 + kc * 32 + lcol));
#pragma unroll
            for (int mf = 0; mf < 2; mf++)
#pragma unroll
                for (int bf = 0; bf < 4; bf++) {
                    mma16816(acc[mf][2 * bf],     Ah[mf][0], Ah[mf][1], Ah[mf][2], Ah[mf][3], B[bf][0], B[bf][2]);
                    mma16816(acc[mf][2 * bf + 1], Ah[mf][0], Ah[mf][1], Ah[mf][2], Ah[mf][3], B[bf][1], B[bf][3]);
                }
        }

        __syncthreads();
        if (q + 2 < 12) {
            int q2 = q + 2;
            stage_w(s32 + ((q2 & 1) ? PJX_W1 : PJX_W0),
                    WH[q2 >> 2], WL[q2 >> 2], (q2 & 3) * 64, t);
        }
        CP_COMMIT();

        if ((q & 3) == 3) {
            if (z == 2) {
#pragma unroll
                for (int mf = 0; mf < 2; mf++) {
                    int nl = wm * 32 + mf * 16 + g;
#pragma unroll
                    for (int nf = 0; nf < 8; nf++) {
                        int o = wn * 64 + nf * 8 + c2;
                        __half h00 = __float2half_rn(acc[mf][nf][0] + bias_s[2][o]);
                        __half h01 = __float2half_rn(acc[mf][nf][1] + bias_s[2][o + 1]);
                        __half h10 = __float2half_rn(acc[mf][nf][2] + bias_s[2][o]);
                        __half h11 = __float2half_rn(acc[mf][nf][3] + bias_s[2][o + 1]);
                        *(__half*)(ps + (o * 128 + nl) * 2)           = h00;
                        *(__half*)(ps + ((o + 1) * 128 + nl) * 2)     = h01;
                        *(__half*)(ps + (o * 128 + nl + 8) * 2)       = h10;
                        *(__half*)(ps + ((o + 1) * 128 + nl + 8) * 2) = h11;
                    }
                }
                __syncthreads();
                int o = t >> 1, part = t & 1;
                __half* dst = g_vt + ((size_t)b * CI + o) * NP + n0 + part * 64;
#pragma unroll
                for (int k = 0; k < 8; k++)
                    *(uint4*)&dst[k * 8] = *(uint4*)(ps + (o * 128 + part * 64 + k * 8) * 2);
            } else {
                __half* dh = (z == 0) ? g_qh : g_kh;
                __half* dc = (z == 0) ? g_qc : g_kc;
                const float sc = (z == 0) ? LOG2E : 1.0f;
                const size_t bq = (size_t)b * NP + n0;
#pragma unroll
                for (int mf = 0; mf < 2; mf++) {
                    int nl = wm * 32 + mf * 16 + g;
#pragma unroll
                    for (int nf = 0; nf < 8; nf++) {
                        int o = wn * 64 + nf * 8 + c2;
                        float bv0 = bias_s[z][o], bv1 = bias_s[z][o + 1];
                        float v[4];
                        v[0] = (acc[mf][nf][0] + bv0) * sc;
                        v[1] = (acc[mf][nf][1] + bv1) * sc;
                        v[2] = (acc[mf][nf][2] + bv0) * sc;
                        v[3] = (acc[mf][nf][3] + bv1) * sc;
                        __half hh[4], cc[4];
#pragma unroll
                        for (int p = 0; p < 4; p++) {
                            __half h = __float2half_rn(v[p]);
                            float  hf = __half2float(h);
                            float  l  = v[p] - hf;
                            hh[p] = h;
                            cc[p] = (z == 0) ? __float2half_rn(hf * 0.015625f + l)
                                             : __float2half_rn(hf + 64.0f * l);
                        }
                        size_t i0 = (bq + nl) * CI + o;
                        size_t i1 = i0 + (size_t)8 * CI;
                        *(u32*)&dh[i0] = h2u(hh[0], hh[1]);
                        *(u32*)&dc[i0] = h2u(cc[0], cc[1]);
                        *(u32*)&dh[i1] = h2u(hh[2], hh[3]);
                        *(u32*)&dc[i1] = h2u(cc[2], cc[3]);
                    }
                }
            }
        }
    }
}

// =================================================================
// Kernel 2: flash attention (R13 version, unchanged — known best).
// =================================================================
#define OFF_QH 0
#define OFF_QC 32768
#define OFF_KH 65536
#define OFF_KC 81920
#define OFF_V  98304
#define SMEM_ATTN 114688
#define KV_TILES 32

__device__ __forceinline__ void load_k(u32 s32, int m0,
                                       const __half* gkh, const __half* gkc, int t)
{
#pragma unroll
    for (int i = 0; i < 8; i++) {
        int id = i * 128 + t;
        int row = id >> 4, c = id & 15;
        u32 sw = SWZ256(row * 256 + c * 16);
        cpa(s32 + OFF_KH + sw, gkh + (size_t)(m0 + row) * CI + c * 8);
        cpa(s32 + OFF_KC + sw, gkc + (size_t)(m0 + row) * CI + c * 8);
    }
}
__device__ __forceinline__ void load_v(u32 s32, int m0, const __half* gvt, int t)
{
#pragma unroll
    for (int i = 0; i < 8; i++) {
        int id = i * 128 + t;
        int row = id >> 3, c = id & 7;
        cpa(s32 + OFF_V + SWZ128(row * 128 + c * 16), gvt + (size_t)row * NP + m0 + c * 8);
    }
}

__global__ __launch_bounds__(128, 2) void attn_kernel()
{
    extern __shared__ __align__(128) char smem[];
    const u32 s32   = smem_u32(smem);
    const int t     = threadIdx.x;
    const int lane  = t & 31;
    const int wr    = (t >> 5) * 32;
    const int row0  = blockIdx.x * 128;
    const int split = blockIdx.y;
    const int b     = blockIdx.z;
    const int kv0   = split * (NP / 2);

    const int lrow = lane & 15;
    const int lcol = (lane >> 4) * 16;
    const int g    = lane >> 2;
    const int c2   = (lane & 3) * 2;

    const __half* gqh = g_qh + ((size_t)b * NP + row0) * CI;
    const __half* gqc = g_qc + ((size_t)b * NP + row0) * CI;
    const __half* gkh = g_kh + ((size_t)b * NP + kv0) * CI;
    const __half* gkc = g_kc + ((size_t)b * NP + kv0) * CI;
    const __half* gvt = g_vt + (size_t)b * CI * NP + kv0;

#pragma unroll
    for (int i = 0; i < 16; i++) {
        int id = i * 128 + t;
        int row = id >> 4, c = id & 15;
        u32 sw = SWZ256(row * 256 + c * 16);
        cpa(s32 + OFF_QH + sw, gqh + (size_t)row * CI + c * 8);
        cpa(s32 + OFF_QC + sw, gqc + (size_t)row * CI + c * 8);
    }
    load_k(s32, 0, gkh, gkc, t);
    CP_COMMIT();
    load_v(s32, 0, gvt, t);
    CP_COMMIT();

    float o[2][16][4];
#pragma unroll
    for (int mf = 0; mf < 2; mf++)
#pragma unroll
        for (int nf = 0; nf < 16; nf++)
#pragma unroll
            for (int q = 0; q < 4; q++) o[mf][nf][q] = 0.0f;
    float mrun[2][2] = {{-1e30f, -1e30f}, {-1e30f, -1e30f}};
    float lrun[2][2] = {{0.0f, 0.0f}, {0.0f, 0.0f}};

    for (int tile = 0; tile < KV_TILES; tile++) {
        CP_WAIT1();
        __syncthreads();

        float s[2][8][4];
#pragma unroll
        for (int mf = 0; mf < 2; mf++)
#pragma unroll
            for (int nf = 0; nf < 8; nf++)
#pragma unroll
                for (int q = 0; q < 4; q++) s[mf][nf][q] = 0.0f;

#pragma unroll
        for (int kc = 0; kc < 8; kc++) {
            u32 qa[2][4];
#pragma unroll
            for (int mf = 0; mf < 2; mf++)
                ldm4(qa[mf][0], qa[mf][1], qa[mf][2], qa[mf][3],
                     s32 + OFF_QH + SWZ256((wr + mf * 16 + lrow) * 256 + kc * 32 + lcol));
#pragma unroll
            for (int nb = 0; nb < 4; nb++) {
                u32 k0, k1, k2, k3;
                ldm4(k0, k1, k2, k3,
                     s32 + OFF_KH + SWZ256((nb * 16 + lrow) * 256 + kc * 32 + lcol));
#pragma unroll
                for (int mf = 0; mf < 2; mf++) {
                    mma16816(s[mf][2 * nb],     qa[mf][0], qa[mf][1], qa[mf][2], qa[mf][3], k0, k2);
                    mma16816(s[mf][2 * nb + 1], qa[mf][0], qa[mf][1], qa[mf][2], qa[mf][3], k1, k3);
                }
            }
        }
#pragma unroll
        for (int mf = 0; mf < 2; mf++)
#pragma unroll
            for (int nf = 0; nf < 8; nf++)
#pragma unroll
                for (int q = 0; q < 4; q++) s[mf][nf][q] *= 0.984375f;

#pragma unroll
        for (int kc = 0; kc < 8; kc++) {
            u32 qa[2][4];
#pragma unroll
            for (int mf = 0; mf < 2; mf++)
                ldm4(qa[mf][0], qa[mf][1], qa[mf][2], qa[mf][3],
                     s32 + OFF_QC + SWZ256((wr + mf * 16 + lrow) * 256 + kc * 32 + lcol));
#pragma unroll
            for (int nb = 0; nb < 4; nb++) {
                u32 k0, k1, k2, k3;
                ldm4(k0, k1, k2, k3,
                     s32 + OFF_KC + SWZ256((nb * 16 + lrow) * 256 + kc * 32 + lcol));
#pragma unroll
                for (int mf = 0; mf < 2; mf++) {
                    mma16816(s[mf][2 * nb],     qa[mf][0], qa[mf][1], qa[mf][2], qa[mf][3], k0, k2);
                    mma16816(s[mf][2 * nb + 1], qa[mf][0], qa[mf][1], qa[mf][2], qa[mf][3], k1, k3);
                }
            }
        }

        __syncthreads();
        if (tile + 1 < KV_TILES) load_k(s32, (tile + 1) * 64, gkh, gkc, t);
        CP_COMMIT();

        // ---- online softmax (f32 ex2; l via ones-MMA) ----
        float corr[2][2];
        u32   p[2][4][4];
#pragma unroll
        for (int mf = 0; mf < 2; mf++) {
            float mx0 = fmaxf(s[mf][0][0], s[mf][0][1]);
            float mx1 = fmaxf(s[mf][0][2], s[mf][0][3]);
#pragma unroll
            for (int nf = 1; nf < 8; nf++) {
                mx0 = fmaxf(mx0, fmaxf(s[mf][nf][0], s[mf][nf][1]));
                mx1 = fmaxf(mx1, fmaxf(s[mf][nf][2], s[mf][nf][3]));
            }
            mx0 = fmaxf(mx0, __shfl_xor_sync(0xffffffffu, mx0, 1));
            mx0 = fmaxf(mx0, __shfl_xor_sync(0xffffffffu, mx0, 2));
            mx1 = fmaxf(mx1, __shfl_xor_sync(0xffffffffu, mx1, 1));
            mx1 = fmaxf(mx1, __shfl_xor_sync(0xffffffffu, mx1, 2));
            float mnew0 = fmaxf(mrun[mf][0], mx0);
            float mnew1 = fmaxf(mrun[mf][1], mx1);
            corr[mf][0] = ex2(mrun[mf][0] - mnew0);
            corr[mf][1] = ex2(mrun[mf][1] - mnew1);
            mrun[mf][0] = mnew0;
            mrun[mf][1] = mnew1;

#pragma unroll
            for (int kc2 = 0; kc2 < 4; kc2++) {
#pragma unroll
                for (int half = 0; half < 2; half++) {
                    int nf = 2 * kc2 + half;
                    float e0 = ex2(s[mf][nf][0] - mnew0);
                    float e1 = ex2(s[mf][nf][1] - mnew0);
                    float e2 = ex2(s[mf][nf][2] - mnew1);
                    float e3 = ex2(s[mf][nf][3] - mnew1);
                    p[mf][kc2][2 * half]     = h2u(__float2half_rn(e0), __float2half_rn(e1));
                    p[mf][kc2][2 * half + 1] = h2u(__float2half_rn(e2), __float2half_rn(e3));
                }
            }
        }

        // l_tile = P . 1  (8 HMMA, no LDS, no shuffles)
        float lc[2][4] = {{0.0f, 0.0f, 0.0f, 0.0f}, {0.0f, 0.0f, 0.0f, 0.0f}};
#pragma unroll
        for (int mf = 0; mf < 2; mf++)
#pragma unroll
            for (int kc2 = 0; kc2 < 4; kc2++)
                mma16816(lc[mf], p[mf][kc2][0], p[mf][kc2][1],
                         p[mf][kc2][2], p[mf][kc2][3], HONE, HONE);
#pragma unroll
        for (int mf = 0; mf < 2; mf++) {
            lrun[mf][0] = lrun[mf][0] * corr[mf][0] + lc[mf][0];
            lrun[mf][1] = lrun[mf][1] * corr[mf][1] + lc[mf][2];
        }

        if (__any_sync(0xffffffffu,
                       fminf(fminf(corr[0][0], corr[0][1]),
                             fminf(corr[1][0], corr[1][1])) < 0.99999f)) {
#pragma unroll
            for (int mf = 0; mf < 2; mf++)
#pragma unroll
                for (int nf = 0; nf < 16; nf++) {
                    o[mf][nf][0] *= corr[mf][0]; o[mf][nf][1] *= corr[mf][0];
                    o[mf][nf][2] *= corr[mf][1]; o[mf][nf][3] *= corr[mf][1];
                }
        }

        CP_WAIT1();
        __syncthreads();

#pragma unroll
        for (int kc2 = 0; kc2 < 4; kc2++) {
#pragma unroll
            for (int dg = 0; dg < 8; dg++) {
                u32 v0, v1, v2, v3;
                ldm4(v0, v1, v2, v3,
                     s32 + OFF_V + SWZ128((dg * 16 + lrow) * 128 + kc2 * 32 + lcol));
#pragma unroll
                for (int mf = 0; mf < 2; mf++) {
                    mma16816(o[mf][2 * dg],
                             p[mf][kc2][0], p[mf][kc2][1], p[mf][kc2][2], p[mf][kc2][3], v0, v2);
                    mma16816(o[mf][2 * dg + 1],
                             p[mf][kc2][0], p[mf][kc2][1], p[mf][kc2][2], p[mf][kc2][3], v1, v3);
                }
            }
        }

        __syncthreads();
        if (tile + 1 < KV_TILES) load_v(s32, (tile + 1) * 64, gvt, t);
        CP_COMMIT();
    }

    float* po = g_po + ((size_t)(split * BB + b) * NP + row0 + wr) * CI;
    float* pm = g_pm + (size_t)(split * BB + b) * NP + row0 + wr;
    float* pl = g_pl + (size_t)(split * BB + b) * NP + row0 + wr;
#pragma unroll
    for (int mf = 0; mf < 2; mf++) {
        int r0 = mf * 16 + g;
#pragma unroll
        for (int nf = 0; nf < 16; nf++) {
            *(float2*)&po[(size_t)r0 * CI + nf * 8 + c2] =
                make_float2(o[mf][nf][0], o[mf][nf][1]);
            *(float2*)&po[(size_t)(r0 + 8) * CI + nf * 8 + c2] =
                make_float2(o[mf][nf][2], o[mf][nf][3]);
        }
        if ((lane & 3) == 0) {
            pm[r0] = mrun[mf][0]; pm[r0 + 8] = mrun[mf][1];
            pl[r0] = lrun[mf][0]; pl[r0 + 8] = lrun[mf][1];
        }
    }
}

// =================================================================
// Kernel 3: fused merge + output projection.
// W for BOTH o-chunks preloaded in the prologue (96KB smem) so the
// chunk loop has no cp.async wait: sync -> stage A -> sync -> mma.
// smem: A_hi 0..16K | A_lo 16..32K | Wh c0 32K | Wh c1 48K |
//       Wl c0 64K | Wl c1 80K   (96KB total, 2 CTAs/SM)
// =================================================================
#define OP_SMEM 98304

__global__ __launch_bounds__(256, 2) void outproj_kernel(
    const float* __restrict__ x, const float* __restrict__ wb,
    float* __restrict__ out)
{
    extern __shared__ char ps[];
    __shared__ float wgt0[128], wgt1[128];
    const u32 s32 = smem_u32(ps);
    const int b  = blockIdx.z;
    const int cb = blockIdx.y * 128;
    const int n0 = blockIdx.x * 128;
    const int t  = threadIdx.x;
    const int lane = t & 31;
    const int w  = t >> 5;
    const int wm = w & 3;
    const int wn = w >> 2;
    const int lrow = lane & 15;
    const int lcol = (lane >> 4) * 16;
    const int g    = lane >> 2;
    const int c2   = (lane & 3) * 2;

    // ---- prologue: preload ALL W (both chunks, hi+lo) ----
#pragma unroll
    for (int i = 0; i < 8; i++) {
        int id = i * 256 + t;
        int row = id >> 3;           // c row 0..255 (wraps into chunk1)
        int ch  = id & 7;            // 16B column
        int chunk = row >> 7;        // 0 or 1
        int r = row & 127;
        u32 sw = SWZ128(r * 128 + ch * 16);
        cpa(s32 + 32768 + chunk * 16384 + sw,
            g_wwh + (size_t)(cb + r) * CI + chunk * 64 + ch * 8);
        cpa(s32 + 65536 + chunk * 16384 + sw,
            g_wwl + (size_t)(cb + r) * CI + chunk * 64 + ch * 8);
    }
    CP_COMMIT();

    if (t < 128) {
        int bn = b * NP + n0 + t;
        float m0 = g_pm[bn], m1 = g_pm[BB * NP + bn];
        float l0 = g_pl[bn], l1 = g_pl[BB * NP + bn];
        float m  = fmaxf(m0, m1);
        float w0 = ex2(m0 - m), w1 = ex2(m1 - m);
        float inv = 1.0f / (w0 * l0 + w1 * l1);
        wgt0[t] = w0 * inv;
        wgt1[t] = w1 * inv;
    }
    CP_WAIT0();
    __syncthreads();

    float acc[2][8][4];
#pragma unroll
    for (int mf = 0; mf < 2; mf++)
#pragma unroll
        for (int nf = 0; nf < 8; nf++)
#pragma unroll
            for (int q = 0; q < 4; q++) acc[mf][nf][q] = 0.0f;

    const float* p0 = g_po + ((size_t)b * NP + n0) * CI;
    const float* p1 = g_po + ((size_t)(BB + b) * NP + n0) * CI;

    for (int o0 = 0; o0 < CI; o0 += 64) {
        const int chunk = o0 >> 6;
        __syncthreads();
        // stage merged A [128n][64o] hi/lo
#pragma unroll
        for (int i = 0; i < 8; i++) {
            int id = i * 256 + t;
            int row = id >> 4, ch = id & 15;
            float4 a = *(const float4*)&p0[(size_t)row * CI + o0 + ch * 4];
            float4 c = *(const float4*)&p1[(size_t)row * CI + o0 + ch * 4];
            float w0 = wgt0[row], w1 = wgt1[row];
            float m[4] = {a.x * w0 + c.x * w1, a.y * w0 + c.y * w1,
                          a.z * w0 + c.z * w1, a.w * w0 + c.w * w1};
            __half h[4], l[4];
#pragma unroll
            for (int q = 0; q < 4; q++) {
                h[q] = __float2half_rn(m[q]);
                l[q] = __float2half_rn(m[q] - __half2float(h[q]));
            }
            u32 sw = SWZ128(row * 128 + ch * 8);
            *(uint2*)(ps + sw)         = make_uint2(h2u(h[0], h[1]), h2u(h[2], h[3]));
            *(uint2*)(ps + 16384 + sw) = make_uint2(h2u(l[0], l[1]), h2u(l[2], l[3]));
        }
        __syncthreads();

        const u32 whb = s32 + 32768 + chunk * 16384;
        const u32 wlb = s32 + 65536 + chunk * 16384;
#pragma unroll
        for (int kc = 0; kc < 4; kc++) {
            u32 Ah[2][4], Al[2][4], B[4][4];
#pragma unroll
            for (int mf = 0; mf < 2; mf++)
                ldm4(Ah[mf][0], Ah[mf][1], Ah[mf][2], Ah[mf][3],
                     s32 + SWZ128((wm * 32 + mf * 16 + lrow) * 128 + kc * 32 + lcol));
#pragma unroll
            for (int bf = 0; bf < 4; bf++)
                ldm4(B[bf][0], B[bf][1], B[bf][2], B[bf][3],
                     whb + SWZ128((wn * 64 + bf * 16 + lrow) * 128 + kc * 32 + lcol));
#pragma unroll
            for (int mf = 0; mf < 2; mf++)
#pragma unroll
                for (int bf = 0; bf < 4; bf++) {
                    mma16816(acc[mf][2 * bf],     Ah[mf][0], Ah[mf][1], Ah[mf][2], Ah[mf][3], B[bf][0], B[bf][2]);
                    mma16816(acc[mf][2 * bf + 1], Ah[mf][0], Ah[mf][1], Ah[mf][2], Ah[mf][3], B[bf][1], B[bf][3]);
                }
#pragma unroll
            for (int mf = 0; mf < 2; mf++)
                ldm4(Al[mf][0], Al[mf][1], Al[mf][2], Al[mf][3],
                     s32 + 16384 + SWZ128((wm * 32 + mf * 16 + lrow) * 128 + kc * 32 + lcol));
#pragma unroll
            for (int mf = 0; mf < 2; mf++)
#pragma unroll
                for (int bf = 0; bf < 4; bf++) {
                    mma16816(acc[mf][2 * bf],     Al[mf][0], Al[mf][1], Al[mf][2], Al[mf][3], B[bf][0], B[bf][2]);
                    mma16816(acc[mf][2 * bf + 1], Al[mf][0], Al[mf][1], Al[mf][2], Al[mf][3], B[bf][1], B[bf][3]);
                }
#pragma unroll
            for (int bf = 0; bf < 4; bf++)
                ldm4(B[bf][0], B[bf][1], B[bf][2], B[bf][3],
                     wlb + SWZ128((wn * 64 + bf * 16 + lrow) * 128 + kc * 32 + lcol));
#pragma unroll
            for (int mf = 0; mf < 2; mf++)
#pragma unroll
                for (int bf = 0; bf < 4; bf++) {
                    mma16816(acc[mf][2 * bf],     Ah[mf][0], Ah[mf][1], Ah[mf][2], Ah[mf][3], B[bf][0], B[bf][2]);
                    mma16816(acc[mf][2 * bf + 1], Ah[mf][0], Ah[mf][1], Ah[mf][2], Ah[mf][3], B[bf][1], B[bf][3]);
                }
        }
    }
    __syncthreads();

    // stage D as [128c][128n] f32 in smem (64KB, reuses A+W regions)
#pragma unroll
    for (int mf = 0; mf < 2; mf++) {
        int nl = wm * 32 + mf * 16 + g;
#pragma unroll
        for (int nf = 0; nf < 8; nf++) {
            int cl = wn * 64 + nf * 8 + c2;
            *(float*)(ps + (cl * 128 + nl) * 4)           = acc[mf][nf][0];
            *(float*)(ps + ((cl + 1) * 128 + nl) * 4)     = acc[mf][nf][1];
            *(float*)(ps + (cl * 128 + nl + 8) * 4)       = acc[mf][nf][2];
            *(float*)(ps + ((cl + 1) * 128 + nl + 8) * 4) = acc[mf][nf][3];
        }
    }
    __syncthreads();

    int r = t >> 1, part = t & 1;
    float bv = wb[cb + r];
    size_t base = ((size_t)b * CC + cb + r) * NP + n0 + part * 64;
#pragma unroll
    for (int k = 0; k < 16; k++) {
        float4 v  = *(float4*)(ps + (r * 128 + part * 64 + k * 4) * 4);
        float4 xv = *(const float4*)&x[base + k * 4];
        float4 rr = make_float4(v.x + bv + xv.x, v.y + bv + xv.y,
                                v.z + bv + xv.z, v.w + bv + xv.w);
        *(float4*)&out[base + k * 4] = rr;
    }
}

// =================================================================
extern "C" void kernel_launch(void* const* d_in, const int* in_sizes, int n_in,
                              void* d_out, int out_size)
{
    const float* x  = (const float*)d_in[0];
    const float* tw = (const float*)d_in[1];
    const float* tb = (const float*)d_in[2];
    const float* pw = (const float*)d_in[3];
    const float* pb = (const float*)d_in[4];
    const float* gw = (const float*)d_in[5];
    const float* gb = (const float*)d_in[6];
    const float* ww = (const float*)d_in[7];
    const float* wb = (const float*)d_in[8];
    float* out = (float*)d_out;

    cudaFuncSetAttribute(attn_kernel,    cudaFuncAttributeMaxDynamicSharedMemorySize, SMEM_ATTN);
    cudaFuncSetAttribute(proj_kernel,    cudaFuncAttributeMaxDynamicSharedMemorySize, PJX_SMEM);
    cudaFuncSetAttribute(outproj_kernel, cudaFuncAttributeMaxDynamicSharedMemorySize, OP_SMEM);

    conv_w<<<128, 256>>>(tw, pw, gw, ww);
    proj_kernel<<<dim3(NP / 128, BB), 256, PJX_SMEM>>>(x, tb, pb, gb);
    attn_kernel<<<dim3(NP / 128, 2, BB), 128, SMEM_ATTN>>>();
    outproj_kernel<<<dim3(NP / 128, CC / 128, BB), 256, OP_SMEM>>>(x, wb, out);
}